// round 10
// baseline (speedup 1.0000x reference)
#include <cuda_runtime.h>
#include <cuda_bf16.h>
#include <math.h>
#include <stdint.h>

// Problem dims (fixed by the dataset)
#define B_   4
#define N_   512
#define C_   1024
#define HID_ 4096
#define NH_  16
#define D_   64
#define R_   (B_*N_)     // 2048 rows per stream
#define R2_  (2*R_)      // 4096 rows: x-stream and y-stream batched
#define EPS_ 1e-5f

// ---------------- scratch (device globals: no allocation allowed) ----------
__device__ float g_zb[R2_*C_];    // concat(x, y) residual stream
__device__ float g_na[R2_*C_];    // ln1 out (fattn input)
// packed (hi/lo, A-fragment layout) activations
__device__ uint32_t g_obh[R2_*C_/2],  g_obl[R2_*C_/2];    // fattn out -> proj A
__device__ uint32_t g_n2h[R2_*C_/2],  g_n2l[R2_*C_/2];    // ln2 out   -> fc1 A
__device__ uint32_t g_hbh[R2_*HID_/2], g_hbl[R2_*HID_/2]; // gelu out  -> fc2 A
// hi/lo-split weights, packed in mma.m16n8k16 B-fragment layout
__device__ uint32_t g_pwh[C_*C_/2],   g_pwl[C_*C_/2];
__device__ uint32_t g_w1h[C_*HID_/2], g_w1l[C_*HID_/2];
__device__ uint32_t g_w2h[HID_*C_/2], g_w2l[HID_*C_/2];

// ======================= helpers =======================
#define CP_ASYNC16(sm, gp) \
    asm volatile("cp.async.cg.shared.global [%0], [%1], 16;" :: "r"(sm), "l"(gp))
#define CP_COMMIT() asm volatile("cp.async.commit_group;" ::: "memory")
#define CP_WAIT0()  asm volatile("cp.async.wait_group 0;" ::: "memory")
#define CP_WAIT1()  asm volatile("cp.async.wait_group 1;" ::: "memory")
#define CP_WAIT2()  asm volatile("cp.async.wait_group 2;" ::: "memory")

__device__ __forceinline__ uint32_t smem_u32(const void* p) {
    uint32_t a;
    asm("{ .reg .u64 t; cvta.to.shared.u64 t, %1; cvt.u32.u64 %0, t; }" : "=r"(a) : "l"(p));
    return a;
}

__device__ __forceinline__ void splitbf(float x, uint16_t& h, uint16_t& l) {
    __nv_bfloat16 bh = __float2bfloat16_rn(x);
    float r = x - __bfloat162float(bh);
    __nv_bfloat16 bl = __float2bfloat16_rn(r);
    h = __bfloat16_as_ushort(bh);
    l = __bfloat16_as_ushort(bl);
}
__device__ __forceinline__ uint32_t pack2(uint16_t lo16, uint16_t hi16) {
    return (uint32_t)lo16 | ((uint32_t)hi16 << 16);
}
__device__ __forceinline__ void split_pack(float a, float b, uint32_t& ph, uint32_t& pl) {
    uint16_t ha, la, hb2, lb2;
    splitbf(a, ha, la); splitbf(b, hb2, lb2);
    ph = pack2(ha, hb2); pl = pack2(la, lb2);
}

__device__ __forceinline__ void mma_bf16(float* c, const uint32_t* a, const uint32_t* b) {
    asm volatile(
        "mma.sync.aligned.m16n8k16.row.col.f32.bf16.bf16.f32 "
        "{%0,%1,%2,%3}, {%4,%5,%6,%7}, {%8,%9}, {%0,%1,%2,%3};"
        : "+f"(c[0]), "+f"(c[1]), "+f"(c[2]), "+f"(c[3])
        : "r"(a[0]), "r"(a[1]), "r"(a[2]), "r"(a[3]), "r"(b[0]), "r"(b[1]));
}

__device__ __forceinline__ float fast_exp(float x) {
    float tt = fmaxf(x * 1.4426950408889634f, -126.0f);
    float fi = floorf(tt);
    float f = tt - fi;
    float p = 0.0013333558f;
    p = fmaf(p, f, 0.0096181291f);
    p = fmaf(p, f, 0.0555041087f);
    p = fmaf(p, f, 0.2402265070f);
    p = fmaf(p, f, 0.6931471806f);
    p = fmaf(p, f, 1.0f);
    return p * __int_as_float((__float2int_rn(fi) + 127) << 23);
}

// ======================= LayerNorm (raw out, for ln1) =======================
__global__ void ln_kernel(const float* __restrict__ in, float* __restrict__ out,
                          const float* __restrict__ gm, const float* __restrict__ bt,
                          const int* guard) {
    if (guard && !guard[0]) return;
    int row = blockIdx.x;
    const float* x = in + (size_t)row * C_;
    float* y = out + (size_t)row * C_;
    float s = 0.f, ss = 0.f;
    for (int i = threadIdx.x; i < C_; i += 256) {
        float v = x[i];
        s += v; ss += v * v;
    }
    __shared__ float red[16];
    for (int o = 16; o; o >>= 1) {
        s  += __shfl_down_sync(0xffffffffu, s, o);
        ss += __shfl_down_sync(0xffffffffu, ss, o);
    }
    int wid = threadIdx.x >> 5, lid = threadIdx.x & 31;
    if (!lid) { red[wid] = s; red[wid + 8] = ss; }
    __syncthreads();
    float mean, rstd;
    {
        float a = 0.f, c2 = 0.f;
        #pragma unroll
        for (int i = 0; i < 8; i++) { a += red[i]; c2 += red[i + 8]; }
        mean = a * (1.0f / C_);
        float var = c2 * (1.0f / C_) - mean * mean;
        rstd = rsqrtf(var + EPS_);
    }
    for (int i = threadIdx.x; i < C_; i += 256) {
        y[i] = (x[i] - mean) * rstd * gm[i] + bt[i];
    }
}

// ============ LayerNorm -> packed hi/lo A-fragments (for ln2 -> fc1) =========
__global__ void __launch_bounds__(256) lnp_kernel(
    const float* __restrict__ in, uint32_t* __restrict__ outH,
    uint32_t* __restrict__ outL, const float* __restrict__ gm,
    const float* __restrict__ bt, const int* guard)
{
    if (guard && !guard[0]) return;
    extern __shared__ __align__(16) char sml[];
    uint32_t* sh = (uint32_t*)sml;
    uint32_t* sl = (uint32_t*)(sml + 32768);
    const int w = threadIdx.x >> 5, lane = threadIdx.x & 31;

    #pragma unroll
    for (int rr = 0; rr < 2; rr++) {
        const int row = blockIdx.x * 16 + w * 2 + rr;
        const float* x = in + (size_t)row * C_;
        float4 v[8];
        float s = 0.f, ss = 0.f;
        #pragma unroll
        for (int i = 0; i < 8; i++) {
            v[i] = *(const float4*)(x + i * 128 + lane * 4);
            s += v[i].x + v[i].y + v[i].z + v[i].w;
            ss += v[i].x * v[i].x + v[i].y * v[i].y + v[i].z * v[i].z + v[i].w * v[i].w;
        }
        #pragma unroll
        for (int o = 16; o; o >>= 1) {
            s  += __shfl_xor_sync(0xffffffffu, s, o);
            ss += __shfl_xor_sync(0xffffffffu, ss, o);
        }
        float mean = s * (1.0f / C_);
        float rstd = rsqrtf(ss * (1.0f / C_) - mean * mean + EPS_);
        const int ag = row & 7, m8 = (row >> 3) & 1;
        const int kin = (lane & 3) * 4;
        const int tt0 = (kin & 7) >> 1, rk = kin >> 3;
        #pragma unroll
        for (int i = 0; i < 8; i++) {
            int c = i * 128 + lane * 4;
            float4 gv = *(const float4*)(gm + c);
            float4 bv = *(const float4*)(bt + c);
            float n0 = (v[i].x - mean) * rstd * gv.x + bv.x;
            float n1 = (v[i].y - mean) * rstd * gv.y + bv.y;
            float n2 = (v[i].z - mean) * rstd * gv.z + bv.z;
            float n3 = (v[i].w - mean) * rstd * gv.w + bv.w;
            int kt = c >> 4;
            int r = m8 + 2 * rk;
            uint32_t ph, pl;
            split_pack(n0, n1, ph, pl);
            int idx0 = (kt * 32 + ag * 4 + tt0) * 4 + r;
            sh[idx0] = ph; sl[idx0] = pl;
            split_pack(n2, n3, ph, pl);
            int idx1 = (kt * 32 + ag * 4 + tt0 + 1) * 4 + r;
            sh[idx1] = ph; sl[idx1] = pl;
        }
    }
    __syncthreads();
    size_t gbase = (size_t)blockIdx.x * 8192;
    #pragma unroll
    for (int q = 0; q < 8; q++) {
        int i = q * 256 + threadIdx.x;
        *(uint4*)(outH + gbase + (size_t)i * 4) = ((const uint4*)sh)[i];
        *(uint4*)(outL + gbase + (size_t)i * 4) = ((const uint4*)sl)[i];
    }
}

// ========== weight prep: hi/lo split + pack into B-fragment layout =========
__global__ void pack_weight(const float* __restrict__ W, uint32_t* __restrict__ hiP,
                            uint32_t* __restrict__ loP, int K, int N) {
    int warp = threadIdx.x >> 5, lane = threadIdx.x & 31;
    int g = lane >> 2, t = lane & 3;
    int ktiles = K >> 4;
    int tiles = (N >> 3) * ktiles;
    for (int tile = blockIdx.x * 8 + warp; tile < tiles; tile += gridDim.x * 8) {
        int ntg = tile / ktiles, ksg = tile % ktiles;
        int n = ntg * 8 + g;
        #pragma unroll
        for (int reg = 0; reg < 2; reg++) {
            int k = ksg * 16 + 2 * t + reg * 8;
            float x0 = W[(size_t)k * N + n];
            float x1 = W[(size_t)(k + 1) * N + n];
            uint16_t h0, l0, h1, l1;
            splitbf(x0, h0, l0);
            splitbf(x1, h1, l1);
            size_t idx = ((size_t)tile * 32 + lane) * 2 + reg;
            hiP[idx] = pack2(h0, h1);
            loP[idx] = pack2(l0, l1);
        }
    }
}

// ======================= bf16-split mma GEMM (packed A + packed B) ==========
// 128x128 CTA tile, K-step 32, FOUR-stage cp.async pipeline (128KB smem,
// wait_group 2 steady-state = 3 iterations of latency cover against
// L2-saturation queuing), 8 warps (2M x 4N), 64x32 warp tile (R6 config).
#define GM_STAGE 32768
#define GM_SMEM  (4 * GM_STAGE)

template <int EPI>
__global__ void __launch_bounds__(256) gemm_mma(
    const uint32_t* __restrict__ AhiP, const uint32_t* __restrict__ AloP,
    const uint32_t* __restrict__ BhiP, const uint32_t* __restrict__ BloP,
    float* __restrict__ Cout, const float* __restrict__ bias,
    const float* __restrict__ res,
    uint32_t* __restrict__ OutHi, uint32_t* __restrict__ OutLo,
    int M, int Nt, int K, const int* guard)
{
    if (guard && !guard[0]) return;
    extern __shared__ __align__(16) char smc[];
    const int tid = threadIdx.x;
    const int warp = tid >> 5, lane = tid & 31;
    const int g = lane >> 2, t = lane & 3;
    const int wm = warp & 1, wn = warp >> 1;
    const int bm = blockIdx.y * 128, bn = blockIdx.x * 128;
    const uint32_t sb = smem_u32(smc);

    const int NIT = K >> 5;
    const int ktiles = K >> 4;
    const int bm16 = bm >> 4, bn8 = bn >> 3;

    auto cpA = [&](int stage, int it) {
        uint32_t dstb = sb + stage * GM_STAGE;
        int kt0 = it * 2;
        #pragma unroll
        for (int q = 0; q < 2; q++) {
            int chunk = q * 256 + tid;
            int mtk = chunk >> 5, j = chunk & 31;
            int mtl = mtk >> 1, ktl = mtk & 1;
            size_t gidx = (((size_t)(bm16 + mtl) * ktiles + kt0 + ktl) * 32 + j) * 4;
            uint32_t dst = dstb + (uint32_t)(mtk * 512 + j * 16);
            CP_ASYNC16(dst, AhiP + gidx);
            CP_ASYNC16(dst + 8192u, AloP + gidx);
        }
    };
    auto cpB = [&](int stage, int it) {
        uint32_t dstb = sb + stage * GM_STAGE + 16384;
        int ksg0 = it * 2;
        #pragma unroll
        for (int q = 0; q < 2; q++) {
            int i = q * 256 + tid;
            int nt = i >> 5, j = i & 31;
            size_t srcoff = (((size_t)(bn8 + nt) * ktiles + ksg0) * 64 + (size_t)j * 4);
            uint32_t dst = dstb + (uint32_t)(nt * 512 + j * 16);
            CP_ASYNC16(dst, BhiP + srcoff);
            CP_ASYNC16(dst + 8192u, BloP + srcoff);
        }
    };

    float acc[4][4][4] = {};

    auto compute = [&](int stage) {
        char* base = smc + stage * GM_STAGE;
        #pragma unroll
        for (int ks = 0; ks < 2; ks++) {
            uint32_t ah[4][4], al[4][4], bh[4][2], bl[4][2];
            #pragma unroll
            for (int mt = 0; mt < 4; mt++) {
                uint32_t off = (uint32_t)(((wm * 4 + mt) * 2 + ks) * 32 + lane) * 16;
                uint4 v = *(const uint4*)(base + off);
                ah[mt][0] = v.x; ah[mt][1] = v.y; ah[mt][2] = v.z; ah[mt][3] = v.w;
                uint4 w = *(const uint4*)(base + 8192 + off);
                al[mt][0] = w.x; al[mt][1] = w.y; al[mt][2] = w.z; al[mt][3] = w.w;
            }
            #pragma unroll
            for (int nt = 0; nt < 4; nt++) {
                uint32_t off = 16384u + (uint32_t)(((wn * 4 + nt) * 2 + ks) * 32 + lane) * 8;
                uint2 v = *(const uint2*)(base + off);
                bh[nt][0] = v.x; bh[nt][1] = v.y;
                uint2 w = *(const uint2*)(base + 8192 + off);
                bl[nt][0] = w.x; bl[nt][1] = w.y;
            }
            #pragma unroll
            for (int mt = 0; mt < 4; mt++)
                #pragma unroll
                for (int nt = 0; nt < 4; nt++) {
                    mma_bf16(acc[mt][nt], ah[mt], bh[nt]);
                    mma_bf16(acc[mt][nt], ah[mt], bl[nt]);
                    mma_bf16(acc[mt][nt], al[mt], bh[nt]);
                }
        }
    };

    // ---- 4-stage pipeline (NIT is always >= 32) ----
    cpA(0, 0); cpB(0, 0); CP_COMMIT();
    cpA(1, 1); cpB(1, 1); CP_COMMIT();
    cpA(2, 2); cpB(2, 2); CP_COMMIT();

    int st = 0;
    for (int it = 0; it < NIT; it++) {
        if (it <= NIT - 3)      { CP_WAIT2(); }
        else if (it == NIT - 2) { CP_WAIT1(); }
        else                    { CP_WAIT0(); }
        __syncthreads();
        if (it + 3 < NIT) {
            int ns = (st + 3) & 3;
            cpA(ns, it + 3); cpB(ns, it + 3); CP_COMMIT();
        }
        compute(st);
        st = (st + 1) & 3;
    }
    __syncthreads();

    if (EPI == 1) {
        #pragma unroll
        for (int mt = 0; mt < 4; mt++) {
            #pragma unroll
            for (int nt = 0; nt < 4; nt++) {
                int row0 = bm + wm * 64 + mt * 16 + g;
                int col = bn + wn * 32 + nt * 8 + t * 2;
                float2 bv = *(const float2*)&bias[col];
                float v0 = acc[mt][nt][0] + bv.x;
                float v1 = acc[mt][nt][1] + bv.y;
                float v2 = acc[mt][nt][2] + bv.x;
                float v3 = acc[mt][nt][3] + bv.y;
                size_t i0 = (size_t)row0 * Nt + col;
                size_t i1 = (size_t)(row0 + 8) * Nt + col;
                float2 r0 = *(const float2*)&res[i0];
                float2 r1 = *(const float2*)&res[i1];
                *(float2*)&Cout[i0] = make_float2(v0 + r0.x, v1 + r0.y);
                *(float2*)&Cout[i1] = make_float2(v2 + r1.x, v3 + r1.y);
            }
        }
    } else {
        uint32_t* sh = (uint32_t*)smc;
        uint32_t* sl = (uint32_t*)(smc + 32768);
        #pragma unroll
        for (int mt = 0; mt < 4; mt++) {
            #pragma unroll
            for (int nt = 0; nt < 4; nt++) {
                int kl = wn * 32 + nt * 8 + t * 2;
                float2 bv = *(const float2*)&bias[bn + kl];
                float v0 = acc[mt][nt][0] + bv.x;
                float v1 = acc[mt][nt][1] + bv.y;
                float v2 = acc[mt][nt][2] + bv.x;
                float v3 = acc[mt][nt][3] + bv.y;
                v0 = 0.5f * v0 * (1.0f + erff(v0 * 0.70710678118654752f));
                v1 = 0.5f * v1 * (1.0f + erff(v1 * 0.70710678118654752f));
                v2 = 0.5f * v2 * (1.0f + erff(v2 * 0.70710678118654752f));
                v3 = 0.5f * v3 * (1.0f + erff(v3 * 0.70710678118654752f));
                int mtl = wm * 4 + mt;
                int ktl = kl >> 4;
                int tt = (kl & 7) >> 1;
                int rk = (kl >> 3) & 1;
                int baseI = ((mtl * 8 + ktl) * 32 + g * 4 + tt) * 4;
                uint32_t ph, pl;
                split_pack(v0, v1, ph, pl);
                sh[baseI + 2 * rk] = ph; sl[baseI + 2 * rk] = pl;
                split_pack(v2, v3, ph, pl);
                sh[baseI + 1 + 2 * rk] = ph; sl[baseI + 1 + 2 * rk] = pl;
            }
        }
        __syncthreads();
        const int ktO = Nt >> 4;
        #pragma unroll
        for (int q = 0; q < 8; q++) {
            int i = q * 256 + tid;
            int mtl = i >> 8, jj = i & 255;
            size_t gidx = (((size_t)(bm16 + mtl) * ktO + (bn >> 4)) * 128) + (size_t)jj * 4;
            *(uint4*)(OutHi + gidx) = ((const uint4*)sh)[i];
            *(uint4*)(OutLo + gidx) = ((const uint4*)sl)[i];
        }
    }
}

// ======================= fused flash attention (tensor cores) ===============
// grid (4 q-tiles, 8*NH). batch bb = blockIdx.y>>4 in 0..7 (x:0-3, y:4-7).
// KV batch = bb ^ kvxor (0 = self, 4 = cross between x and y halves).
#define FA_QH 0
#define FA_QL 16384
#define FA_KH 32768
#define FA_KL 49152
#define FA_VH 65536
#define FA_VL 81920
#define FA_SMEM 98304

__global__ void __launch_bounds__(256, 1) fattn_kernel(
    const float* __restrict__ NA, int kvxor,
    uint32_t* __restrict__ Ohi, uint32_t* __restrict__ Olo, const int* guard)
{
    if (guard && !guard[0]) return;
    extern __shared__ __align__(16) char smf[];
    const int tid = threadIdx.x, lane = tid & 31, warp = tid >> 5;
    const int g = lane >> 2, t = lane & 3;
    const int bh = blockIdx.y, b = bh >> 4, h = bh & 15;
    const int n0 = blockIdx.x * 128;
    const float* Qb = NA + (size_t)b * N_ * C_ + h * D_;
    const float* Kb = NA + (size_t)(b ^ kvxor) * N_ * C_ + h * D_;

    // ---- Q -> A-fragments (hi/lo), scaled by 1/8 ----
    {
        const int arow = tid >> 1, hf = tid & 1;
        const float* qp = Qb + (size_t)(n0 + arow) * C_ + hf * 32;
        const int mtile = arow >> 4, ag = arow & 7, arm = (arow >> 3) & 1;
        #pragma unroll
        for (int q4 = 0; q4 < 8; q4++) {
            float4 v = *(const float4*)(qp + q4 * 4);
            float xs[4] = {v.x * 0.125f, v.y * 0.125f, v.z * 0.125f, v.w * 0.125f};
            #pragma unroll
            for (int p = 0; p < 2; p++) {
                int d = hf * 32 + q4 * 4 + 2 * p;
                uint32_t ph, pl;
                split_pack(xs[2 * p], xs[2 * p + 1], ph, pl);
                int kt = d >> 4, kin = d & 15;
                int tt = (kin & 7) >> 1, rk = kin >> 3;
                uint32_t idx = (uint32_t)(((mtile * 4 + kt) * 32 + ag * 4 + tt) * 4 + (arm + 2 * rk));
                *(uint32_t*)(smf + FA_QH + idx * 4) = ph;
                *(uint32_t*)(smf + FA_QL + idx * 4) = pl;
            }
        }
    }
    __syncthreads();

    uint32_t qh[4][4], ql[4][4];
    #pragma unroll
    for (int kt = 0; kt < 4; kt++) {
        uint4 v = *(const uint4*)(smf + FA_QH + (size_t)(((warp * 4 + kt) * 32 + lane) * 4) * 4);
        qh[kt][0] = v.x; qh[kt][1] = v.y; qh[kt][2] = v.z; qh[kt][3] = v.w;
        uint4 w = *(const uint4*)(smf + FA_QL + (size_t)(((warp * 4 + kt) * 32 + lane) * 4) * 4);
        ql[kt][0] = w.x; ql[kt][1] = w.y; ql[kt][2] = w.z; ql[kt][3] = w.w;
    }

    float o[8][4] = {};
    float m0 = -1e30f, m1 = -1e30f, l0 = 0.f, l1 = 0.f;

    for (int ch = 0; ch < 4; ch++) {
        const int s0 = ch * 128;
        __syncthreads();
        // ---- K chunk -> B-frags ----
        {
            const int r = tid >> 1, hf = tid & 1;
            const float* kp = Kb + (size_t)(s0 + r) * C_ + hf * 32;
            const int ntile = r >> 3, kg = r & 7;
            #pragma unroll
            for (int q4 = 0; q4 < 8; q4++) {
                float4 v = *(const float4*)(kp + q4 * 4);
                float xs[4] = {v.x, v.y, v.z, v.w};
                #pragma unroll
                for (int p = 0; p < 2; p++) {
                    int d = hf * 32 + q4 * 4 + 2 * p;
                    uint32_t ph, pl;
                    split_pack(xs[2 * p], xs[2 * p + 1], ph, pl);
                    int kt = d >> 4;
                    int lanef = kg * 4 + ((d & 7) >> 1);
                    int reg = ((d & 15) >= 8) ? 1 : 0;
                    uint32_t idx = (uint32_t)(((ntile * 4 + kt) * 32 + lanef) * 2 + reg);
                    *(uint32_t*)(smf + FA_KH + idx * 4) = ph;
                    *(uint32_t*)(smf + FA_KL + idx * 4) = pl;
                }
            }
        }
        // ---- V chunk -> B-frags (n=d, k=s) ----
        {
            const int sp = tid & 63, dq = tid >> 6;
            const float* vp = Kb + (size_t)(s0 + 2 * sp) * C_ + dq * 16;
            #pragma unroll
            for (int q4 = 0; q4 < 4; q4++) {
                float4 a = *(const float4*)(vp + q4 * 4);
                float4 c = *(const float4*)(vp + C_ + q4 * 4);
                float as[4] = {a.x, a.y, a.z, a.w};
                float cs[4] = {c.x, c.y, c.z, c.w};
                #pragma unroll
                for (int e = 0; e < 4; e++) {
                    int d = dq * 16 + q4 * 4 + e;
                    uint32_t ph, pl;
                    split_pack(as[e], cs[e], ph, pl);
                    int dnt = d >> 3, skt = sp >> 3;
                    int lanef = (d & 7) * 4 + (sp & 3);
                    int reg = (sp >> 2) & 1;
                    uint32_t idx = (uint32_t)(((dnt * 8 + skt) * 32 + lanef) * 2 + reg);
                    *(uint32_t*)(smf + FA_VH + idx * 4) = ph;
                    *(uint32_t*)(smf + FA_VL + idx * 4) = pl;
                }
            }
        }
        __syncthreads();

        // ---- S = Q @ K^T (3-term) ----
        float s[16][4];
        #pragma unroll
        for (int nt = 0; nt < 16; nt++) { s[nt][0] = s[nt][1] = s[nt][2] = s[nt][3] = 0.f; }
        #pragma unroll
        for (int nt = 0; nt < 16; nt++) {
            #pragma unroll
            for (int kt = 0; kt < 4; kt++) {
                uint32_t kh[2], kl[2];
                uint2 a = *(const uint2*)(smf + FA_KH + (size_t)(((nt * 4 + kt) * 32 + lane) * 2) * 4);
                kh[0] = a.x; kh[1] = a.y;
                uint2 c = *(const uint2*)(smf + FA_KL + (size_t)(((nt * 4 + kt) * 32 + lane) * 2) * 4);
                kl[0] = c.x; kl[1] = c.y;
                mma_bf16(s[nt], qh[kt], kh);
                mma_bf16(s[nt], qh[kt], kl);
                mma_bf16(s[nt], ql[kt], kh);
            }
        }

        // ---- online softmax ----
        float cm0 = -1e30f, cm1 = -1e30f;
        #pragma unroll
        for (int nt = 0; nt < 16; nt++) {
            cm0 = fmaxf(cm0, fmaxf(s[nt][0], s[nt][1]));
            cm1 = fmaxf(cm1, fmaxf(s[nt][2], s[nt][3]));
        }
        cm0 = fmaxf(cm0, __shfl_xor_sync(0xffffffffu, cm0, 1));
        cm0 = fmaxf(cm0, __shfl_xor_sync(0xffffffffu, cm0, 2));
        cm1 = fmaxf(cm1, __shfl_xor_sync(0xffffffffu, cm1, 1));
        cm1 = fmaxf(cm1, __shfl_xor_sync(0xffffffffu, cm1, 2));
        float nm0 = fmaxf(m0, cm0), nm1 = fmaxf(m1, cm1);
        float al0 = fast_exp(m0 - nm0), al1 = fast_exp(m1 - nm1);
        m0 = nm0; m1 = nm1;
        #pragma unroll
        for (int dnt = 0; dnt < 8; dnt++) {
            o[dnt][0] *= al0; o[dnt][1] *= al0;
            o[dnt][2] *= al1; o[dnt][3] *= al1;
        }
        float ls0 = 0.f, ls1 = 0.f;

        #pragma unroll
        for (int kt = 0; kt < 8; kt++) {
            float p00 = fast_exp(s[2 * kt][0] - m0);
            float p01 = fast_exp(s[2 * kt][1] - m0);
            float p02 = fast_exp(s[2 * kt][2] - m1);
            float p03 = fast_exp(s[2 * kt][3] - m1);
            float p10 = fast_exp(s[2 * kt + 1][0] - m0);
            float p11 = fast_exp(s[2 * kt + 1][1] - m0);
            float p12 = fast_exp(s[2 * kt + 1][2] - m1);
            float p13 = fast_exp(s[2 * kt + 1][3] - m1);
            ls0 += p00 + p01 + p10 + p11;
            ls1 += p02 + p03 + p12 + p13;
            uint32_t ph[4], pl[4];
            split_pack(p00, p01, ph[0], pl[0]);
            split_pack(p02, p03, ph[1], pl[1]);
            split_pack(p10, p11, ph[2], pl[2]);
            split_pack(p12, p13, ph[3], pl[3]);
            #pragma unroll
            for (int dnt = 0; dnt < 8; dnt++) {
                uint32_t vh[2], vl[2];
                uint2 a = *(const uint2*)(smf + FA_VH + (size_t)(((dnt * 8 + kt) * 32 + lane) * 2) * 4);
                vh[0] = a.x; vh[1] = a.y;
                uint2 c = *(const uint2*)(smf + FA_VL + (size_t)(((dnt * 8 + kt) * 32 + lane) * 2) * 4);
                vl[0] = c.x; vl[1] = c.y;
                mma_bf16(o[dnt], ph, vh);
                mma_bf16(o[dnt], ph, vl);
                mma_bf16(o[dnt], pl, vh);
            }
        }
        ls0 += __shfl_xor_sync(0xffffffffu, ls0, 1);
        ls0 += __shfl_xor_sync(0xffffffffu, ls0, 2);
        ls1 += __shfl_xor_sync(0xffffffffu, ls1, 1);
        ls1 += __shfl_xor_sync(0xffffffffu, ls1, 2);
        l0 = l0 * al0 + ls0;
        l1 = l1 * al1 + ls1;
    }

    // ---- packed epilogue ----
    __syncthreads();
    uint32_t* sh = (uint32_t*)(smf + FA_KH);
    uint32_t* sl = (uint32_t*)(smf + FA_KL);
    float inv0 = 1.0f / l0, inv1 = 1.0f / l1;
    #pragma unroll
    for (int dnt = 0; dnt < 8; dnt++) {
        int kl_ = dnt * 8 + 2 * t;
        int ktl = kl_ >> 4;
        int rk = dnt & 1;
        int baseI = ((warp * 4 + ktl) * 32 + lane) * 4;
        uint32_t ph, pl;
        split_pack(o[dnt][0] * inv0, o[dnt][1] * inv0, ph, pl);
        sh[baseI + 2 * rk] = ph; sl[baseI + 2 * rk] = pl;
        split_pack(o[dnt][2] * inv1, o[dnt][3] * inv1, ph, pl);
        sh[baseI + 1 + 2 * rk] = ph; sl[baseI + 1 + 2 * rk] = pl;
    }
    __syncthreads();
    #pragma unroll
    for (int q = 0; q < 4; q++) {
        int i = q * 256 + tid;
        int mtl = i >> 7, jj = i & 127;
        size_t gidx = (((size_t)(b * 32 + blockIdx.x * 8 + mtl) * 64) + h * 4) * 128 + (size_t)jj * 4;
        *(uint4*)(Ohi + gidx) = ((const uint4*)sh)[i];
        *(uint4*)(Olo + gidx) = ((const uint4*)sl)[i];
    }
}

// ======================= host orchestration =======================
struct Weights {
    const float *n1g, *n1b, *n2g, *n2b, *pw, *pb, *w1, *b1, *w2, *b2;
};
struct Bufs {
    float *zb, *na;
    uint32_t *obh, *obl, *n2h, *n2l, *hbh, *hbl;
    uint32_t *pwh, *pwl, *w1h, *w1l, *w2h, *w2l;
};

// One full transformer block over the batched 4096-row stream.
static void block_batched(float* resbuf, float* outbuf, int kvxor,
                          const Bufs& B, const Weights& W, const int* guard) {
    ln_kernel<<<R2_, 256>>>(resbuf, B.na, W.n1g, W.n1b, guard);
    fattn_kernel<<<dim3(4, 8 * NH_), 256, FA_SMEM>>>(B.na, kvxor, B.obh, B.obl, guard);
    gemm_mma<1><<<dim3(C_ / 128, R2_ / 128), 256, GM_SMEM>>>(
        B.obh, B.obl, B.pwh, B.pwl, outbuf, W.pb, resbuf, nullptr, nullptr,
        R2_, C_, C_, guard);
    lnp_kernel<<<R2_ / 16, 256, 65536>>>(outbuf, B.n2h, B.n2l, W.n2g, W.n2b, guard);
    gemm_mma<2><<<dim3(HID_ / 128, R2_ / 128), 256, GM_SMEM>>>(
        B.n2h, B.n2l, B.w1h, B.w1l, nullptr, W.b1, nullptr, B.hbh, B.hbl,
        R2_, HID_, C_, guard);
    gemm_mma<1><<<dim3(C_ / 128, R2_ / 128), 256, GM_SMEM>>>(
        B.hbh, B.hbl, B.w2h, B.w2l, outbuf, W.b2, outbuf, nullptr, nullptr,
        R2_, C_, HID_, guard);
}

extern "C" void kernel_launch(void* const* d_in, const int* in_sizes, int n_in,
                              void* d_out, int out_size) {
    const float* x   = (const float*)d_in[0];
    const float* y   = (const float*)d_in[1];
    Weights W;
    W.n1g = (const float*)d_in[2];  W.n1b = (const float*)d_in[3];
    W.n2g = (const float*)d_in[4];  W.n2b = (const float*)d_in[5];
    W.pw  = (const float*)d_in[6];  W.pb  = (const float*)d_in[7];
    W.w1  = (const float*)d_in[8];  W.b1  = (const float*)d_in[9];
    W.w2  = (const float*)d_in[10]; W.b2  = (const float*)d_in[11];
    const int* flag = (const int*)d_in[12];
    float* out = (float*)d_out;    // 4096 x 1024 = concat(x1, y1)

    Bufs B;
    cudaGetSymbolAddress((void**)&B.zb, g_zb);
    cudaGetSymbolAddress((void**)&B.na, g_na);
    cudaGetSymbolAddress((void**)&B.obh, g_obh);
    cudaGetSymbolAddress((void**)&B.obl, g_obl);
    cudaGetSymbolAddress((void**)&B.n2h, g_n2h);
    cudaGetSymbolAddress((void**)&B.n2l, g_n2l);
    cudaGetSymbolAddress((void**)&B.hbh, g_hbh);
    cudaGetSymbolAddress((void**)&B.hbl, g_hbl);
    cudaGetSymbolAddress((void**)&B.pwh, g_pwh);
    cudaGetSymbolAddress((void**)&B.pwl, g_pwl);
    cudaGetSymbolAddress((void**)&B.w1h, g_w1h);
    cudaGetSymbolAddress((void**)&B.w1l, g_w1l);
    cudaGetSymbolAddress((void**)&B.w2h, g_w2h);
    cudaGetSymbolAddress((void**)&B.w2l, g_w2l);

    cudaFuncSetAttribute(gemm_mma<1>, cudaFuncAttributeMaxDynamicSharedMemorySize, GM_SMEM);
    cudaFuncSetAttribute(gemm_mma<2>, cudaFuncAttributeMaxDynamicSharedMemorySize, GM_SMEM);
    cudaFuncSetAttribute(fattn_kernel, cudaFuncAttributeMaxDynamicSharedMemorySize, FA_SMEM);
    cudaFuncSetAttribute(lnp_kernel, cudaFuncAttributeMaxDynamicSharedMemorySize, 65536);

    // weight prep (runs every launch; ~25us)
    pack_weight<<<512, 256>>>(W.pw, B.pwh, B.pwl, C_, C_);
    pack_weight<<<512, 256>>>(W.w1, B.w1h, B.w1l, C_, HID_);
    pack_weight<<<512, 256>>>(W.w2, B.w2h, B.w2l, HID_, C_);

    const size_t bytes = (size_t)R_ * C_ * sizeof(float);
    cudaMemcpyAsync(B.zb, x, bytes, cudaMemcpyDeviceToDevice);
    cudaMemcpyAsync(B.zb + (size_t)R_ * C_, y, bytes, cudaMemcpyDeviceToDevice);

    // x and y self-chains batched as 8 "batches" (x:0-3, y:4-7). Only the
    // FINAL iteration's cross block is live: 4 gated self blocks, then one
    // cross block (kv from opposite half).
    for (int it = 0; it < 4; it++) {
        block_batched(B.zb, B.zb, 0, B, W, flag);
    }
    block_batched(B.zb, out, 4, B, W, nullptr);
}

// round 11
// speedup vs baseline: 1.9593x; 1.9593x over previous
#include <cuda_runtime.h>
#include <cuda_bf16.h>
#include <cuda_fp16.h>
#include <math.h>
#include <stdint.h>

// Problem dims (fixed by the dataset)
#define B_   4
#define N_   512
#define C_   1024
#define HID_ 4096
#define NH_  16
#define D_   64
#define R_   (B_*N_)     // 2048 rows per stream
#define R2_  (2*R_)      // 4096 rows: x-stream and y-stream batched
#define EPS_ 1e-5f

// ---------------- scratch (device globals: no allocation allowed) ----------
__device__ float g_zb[R2_*C_];    // concat(x, y) residual stream
__device__ float g_na[R2_*C_];    // ln1 out (fattn input)
// fp16-packed (A-fragment layout) activations
__device__ uint32_t g_obh[R2_*C_/2];    // fattn out -> proj A
__device__ uint32_t g_n2h[R2_*C_/2];    // ln2 out   -> fc1 A
__device__ uint32_t g_hbh[R2_*HID_/2];  // gelu out  -> fc2 A
// fp16 weights packed in mma.m16n8k16 B-fragment layout
__device__ uint32_t g_pwh[C_*C_/2];
__device__ uint32_t g_w1h[C_*HID_/2];
__device__ uint32_t g_w2h[HID_*C_/2];

// ======================= helpers =======================
#define CP_ASYNC16(sm, gp) \
    asm volatile("cp.async.cg.shared.global [%0], [%1], 16;" :: "r"(sm), "l"(gp))
#define CP_COMMIT() asm volatile("cp.async.commit_group;" ::: "memory")
#define CP_WAIT0()  asm volatile("cp.async.wait_group 0;" ::: "memory")
#define CP_WAIT1()  asm volatile("cp.async.wait_group 1;" ::: "memory")

__device__ __forceinline__ uint32_t smem_u32(const void* p) {
    uint32_t a;
    asm("{ .reg .u64 t; cvta.to.shared.u64 t, %1; cvt.u32.u64 %0, t; }" : "=r"(a) : "l"(p));
    return a;
}

// bf16 hi/lo split helpers (used only by flash attention)
__device__ __forceinline__ void splitbf(float x, uint16_t& h, uint16_t& l) {
    __nv_bfloat16 bh = __float2bfloat16_rn(x);
    float r = x - __bfloat162float(bh);
    __nv_bfloat16 bl = __float2bfloat16_rn(r);
    h = __bfloat16_as_ushort(bh);
    l = __bfloat16_as_ushort(bl);
}
__device__ __forceinline__ uint32_t pack2(uint16_t lo16, uint16_t hi16) {
    return (uint32_t)lo16 | ((uint32_t)hi16 << 16);
}
__device__ __forceinline__ void split_pack(float a, float b, uint32_t& ph, uint32_t& pl) {
    uint16_t ha, la, hb2, lb2;
    splitbf(a, ha, la); splitbf(b, hb2, lb2);
    ph = pack2(ha, hb2); pl = pack2(la, lb2);
}
// fp16 pair pack (low half = first element)
__device__ __forceinline__ uint32_t packh2(float a, float b) {
    __half2 h = __halves2half2(__float2half_rn(a), __float2half_rn(b));
    return *(uint32_t*)&h;
}

__device__ __forceinline__ void mma_bf16(float* c, const uint32_t* a, const uint32_t* b) {
    asm volatile(
        "mma.sync.aligned.m16n8k16.row.col.f32.bf16.bf16.f32 "
        "{%0,%1,%2,%3}, {%4,%5,%6,%7}, {%8,%9}, {%0,%1,%2,%3};"
        : "+f"(c[0]), "+f"(c[1]), "+f"(c[2]), "+f"(c[3])
        : "r"(a[0]), "r"(a[1]), "r"(a[2]), "r"(a[3]), "r"(b[0]), "r"(b[1]));
}
__device__ __forceinline__ void mma_f16(float* c, const uint32_t* a, const uint32_t* b) {
    asm volatile(
        "mma.sync.aligned.m16n8k16.row.col.f32.f16.f16.f32 "
        "{%0,%1,%2,%3}, {%4,%5,%6,%7}, {%8,%9}, {%0,%1,%2,%3};"
        : "+f"(c[0]), "+f"(c[1]), "+f"(c[2]), "+f"(c[3])
        : "r"(a[0]), "r"(a[1]), "r"(a[2]), "r"(a[3]), "r"(b[0]), "r"(b[1]));
}

__device__ __forceinline__ float fast_exp(float x) {
    float tt = fmaxf(x * 1.4426950408889634f, -126.0f);
    float fi = floorf(tt);
    float f = tt - fi;
    float p = 0.0013333558f;
    p = fmaf(p, f, 0.0096181291f);
    p = fmaf(p, f, 0.0555041087f);
    p = fmaf(p, f, 0.2402265070f);
    p = fmaf(p, f, 0.6931471806f);
    p = fmaf(p, f, 1.0f);
    return p * __int_as_float((__float2int_rn(fi) + 127) << 23);
}

// ======================= LayerNorm (raw out, for ln1) =======================
__global__ void ln_kernel(const float* __restrict__ in, float* __restrict__ out,
                          const float* __restrict__ gm, const float* __restrict__ bt,
                          const int* guard) {
    if (guard && !guard[0]) return;
    int row = blockIdx.x;
    const float* x = in + (size_t)row * C_;
    float* y = out + (size_t)row * C_;
    float s = 0.f, ss = 0.f;
    for (int i = threadIdx.x; i < C_; i += 256) {
        float v = x[i];
        s += v; ss += v * v;
    }
    __shared__ float red[16];
    for (int o = 16; o; o >>= 1) {
        s  += __shfl_down_sync(0xffffffffu, s, o);
        ss += __shfl_down_sync(0xffffffffu, ss, o);
    }
    int wid = threadIdx.x >> 5, lid = threadIdx.x & 31;
    if (!lid) { red[wid] = s; red[wid + 8] = ss; }
    __syncthreads();
    float mean, rstd;
    {
        float a = 0.f, c2 = 0.f;
        #pragma unroll
        for (int i = 0; i < 8; i++) { a += red[i]; c2 += red[i + 8]; }
        mean = a * (1.0f / C_);
        float var = c2 * (1.0f / C_) - mean * mean;
        rstd = rsqrtf(var + EPS_);
    }
    for (int i = threadIdx.x; i < C_; i += 256) {
        y[i] = (x[i] - mean) * rstd * gm[i] + bt[i];
    }
}

// ============ LayerNorm -> packed fp16 A-fragments (for ln2 -> fc1) =========
__global__ void __launch_bounds__(256) lnp_kernel(
    const float* __restrict__ in, uint32_t* __restrict__ outH,
    const float* __restrict__ gm, const float* __restrict__ bt,
    const int* guard)
{
    if (guard && !guard[0]) return;
    extern __shared__ __align__(16) char sml[];
    uint32_t* sh = (uint32_t*)sml;              // 8192 u32 (32KB)
    const int w = threadIdx.x >> 5, lane = threadIdx.x & 31;

    #pragma unroll
    for (int rr = 0; rr < 2; rr++) {
        const int row = blockIdx.x * 16 + w * 2 + rr;
        const float* x = in + (size_t)row * C_;
        float4 v[8];
        float s = 0.f, ss = 0.f;
        #pragma unroll
        for (int i = 0; i < 8; i++) {
            v[i] = *(const float4*)(x + i * 128 + lane * 4);
            s += v[i].x + v[i].y + v[i].z + v[i].w;
            ss += v[i].x * v[i].x + v[i].y * v[i].y + v[i].z * v[i].z + v[i].w * v[i].w;
        }
        #pragma unroll
        for (int o = 16; o; o >>= 1) {
            s  += __shfl_xor_sync(0xffffffffu, s, o);
            ss += __shfl_xor_sync(0xffffffffu, ss, o);
        }
        float mean = s * (1.0f / C_);
        float rstd = rsqrtf(ss * (1.0f / C_) - mean * mean + EPS_);
        const int ag = row & 7, m8 = (row >> 3) & 1;
        const int kin = (lane & 3) * 4;
        const int tt0 = (kin & 7) >> 1, rk = kin >> 3;
        #pragma unroll
        for (int i = 0; i < 8; i++) {
            int c = i * 128 + lane * 4;
            float4 gv = *(const float4*)(gm + c);
            float4 bv = *(const float4*)(bt + c);
            float n0 = (v[i].x - mean) * rstd * gv.x + bv.x;
            float n1 = (v[i].y - mean) * rstd * gv.y + bv.y;
            float n2 = (v[i].z - mean) * rstd * gv.z + bv.z;
            float n3 = (v[i].w - mean) * rstd * gv.w + bv.w;
            int kt = c >> 4;
            int r = m8 + 2 * rk;
            sh[(kt * 32 + ag * 4 + tt0) * 4 + r] = packh2(n0, n1);
            sh[(kt * 32 + ag * 4 + tt0 + 1) * 4 + r] = packh2(n2, n3);
        }
    }
    __syncthreads();
    size_t gbase = (size_t)blockIdx.x * 8192;
    #pragma unroll
    for (int q = 0; q < 8; q++) {
        int i = q * 256 + threadIdx.x;
        *(uint4*)(outH + gbase + (size_t)i * 4) = ((const uint4*)sh)[i];
    }
}

// ========== weight prep: fp16 pack into B-fragment layout =========
__global__ void pack_weight(const float* __restrict__ W, uint32_t* __restrict__ hiP,
                            int K, int N) {
    int warp = threadIdx.x >> 5, lane = threadIdx.x & 31;
    int g = lane >> 2, t = lane & 3;
    int ktiles = K >> 4;
    int tiles = (N >> 3) * ktiles;
    for (int tile = blockIdx.x * 8 + warp; tile < tiles; tile += gridDim.x * 8) {
        int ntg = tile / ktiles, ksg = tile % ktiles;
        int n = ntg * 8 + g;
        #pragma unroll
        for (int reg = 0; reg < 2; reg++) {
            int k = ksg * 16 + 2 * t + reg * 8;
            float x0 = W[(size_t)k * N + n];
            float x1 = W[(size_t)(k + 1) * N + n];
            hiP[((size_t)tile * 32 + lane) * 2 + reg] = packh2(x0, x1);
        }
    }
}

// ======================= fp16 mma GEMM (packed A + packed B) ==========
// 128x128 CTA tile, K-step 32, 3-stage cp.async pipeline, 8 warps (2M x 4N).
// Stage (16KB): A[0,8K) B[8K,16K).
#define GM_STAGE 16384
#define GM_SMEM  (3 * GM_STAGE)

template <int EPI>
__global__ void __launch_bounds__(256) gemm_mma(
    const uint32_t* __restrict__ AP, const uint32_t* __restrict__ BP,
    float* __restrict__ Cout, const float* __restrict__ bias,
    const float* __restrict__ res, uint32_t* __restrict__ OutHi,
    int M, int Nt, int K, const int* guard)
{
    if (guard && !guard[0]) return;
    extern __shared__ __align__(16) char smc[];
    const int tid = threadIdx.x;
    const int warp = tid >> 5, lane = tid & 31;
    const int g = lane >> 2, t = lane & 3;
    const int wm = warp & 1, wn = warp >> 1;
    const int bm = blockIdx.y * 128, bn = blockIdx.x * 128;
    const uint32_t sb = smem_u32(smc);

    const int NIT = K >> 5;
    const int ktiles = K >> 4;
    const int bm16 = bm >> 4, bn8 = bn >> 3;

    auto cpA = [&](int stage, int it) {
        uint32_t dstb = sb + stage * GM_STAGE;
        int kt0 = it * 2;
        #pragma unroll
        for (int q = 0; q < 2; q++) {
            int chunk = q * 256 + tid;        // 0..511
            int mtk = chunk >> 5, j = chunk & 31;
            int mtl = mtk >> 1, ktl = mtk & 1;
            size_t gidx = (((size_t)(bm16 + mtl) * ktiles + kt0 + ktl) * 32 + j) * 4;
            CP_ASYNC16(dstb + (uint32_t)(mtk * 512 + j * 16), AP + gidx);
        }
    };
    auto cpB = [&](int stage, int it) {
        uint32_t dstb = sb + stage * GM_STAGE + 8192u;
        int ksg0 = it * 2;
        #pragma unroll
        for (int q = 0; q < 2; q++) {
            int i = q * 256 + tid;            // 0..511
            int nt = i >> 5, j = i & 31;
            size_t srcoff = (((size_t)(bn8 + nt) * ktiles + ksg0) * 64 + (size_t)j * 4);
            CP_ASYNC16(dstb + (uint32_t)(nt * 512 + j * 16), BP + srcoff);
        }
    };

    float acc[4][4][4] = {};

    auto compute = [&](int stage) {
        char* base = smc + stage * GM_STAGE;
        #pragma unroll
        for (int ks = 0; ks < 2; ks++) {
            uint32_t ah[4][4], bh[4][2];
            #pragma unroll
            for (int mt = 0; mt < 4; mt++) {
                uint32_t off = (uint32_t)(((wm * 4 + mt) * 2 + ks) * 32 + lane) * 16;
                uint4 v = *(const uint4*)(base + off);
                ah[mt][0] = v.x; ah[mt][1] = v.y; ah[mt][2] = v.z; ah[mt][3] = v.w;
            }
            #pragma unroll
            for (int nt = 0; nt < 4; nt++) {
                uint32_t off = 8192u + (uint32_t)(((wn * 4 + nt) * 2 + ks) * 32 + lane) * 8;
                uint2 v = *(const uint2*)(base + off);
                bh[nt][0] = v.x; bh[nt][1] = v.y;
            }
            #pragma unroll
            for (int mt = 0; mt < 4; mt++)
                #pragma unroll
                for (int nt = 0; nt < 4; nt++)
                    mma_f16(acc[mt][nt], ah[mt], bh[nt]);
        }
    };

    cpA(0, 0); cpB(0, 0); CP_COMMIT();
    cpA(1, 1); cpB(1, 1); CP_COMMIT();

    int st = 0;
    for (int it = 0; it < NIT; it++) {
        if (it + 1 < NIT) { CP_WAIT1(); } else { CP_WAIT0(); }
        __syncthreads();
        if (it + 2 < NIT) {
            int ns = st + 2; if (ns >= 3) ns -= 3;
            cpA(ns, it + 2); cpB(ns, it + 2); CP_COMMIT();
        }
        compute(st);
        if (++st == 3) st = 0;
    }
    __syncthreads();

    if (EPI == 1) {
        #pragma unroll
        for (int mt = 0; mt < 4; mt++) {
            #pragma unroll
            for (int nt = 0; nt < 4; nt++) {
                int row0 = bm + wm * 64 + mt * 16 + g;
                int col = bn + wn * 32 + nt * 8 + t * 2;
                float2 bv = *(const float2*)&bias[col];
                float v0 = acc[mt][nt][0] + bv.x;
                float v1 = acc[mt][nt][1] + bv.y;
                float v2 = acc[mt][nt][2] + bv.x;
                float v3 = acc[mt][nt][3] + bv.y;
                size_t i0 = (size_t)row0 * Nt + col;
                size_t i1 = (size_t)(row0 + 8) * Nt + col;
                float2 r0 = *(const float2*)&res[i0];
                float2 r1 = *(const float2*)&res[i1];
                *(float2*)&Cout[i0] = make_float2(v0 + r0.x, v1 + r0.y);
                *(float2*)&Cout[i1] = make_float2(v2 + r1.x, v3 + r1.y);
            }
        }
    } else {
        // GELU -> packed fp16 A-fragments (32KB staged in smem)
        uint32_t* sh = (uint32_t*)smc;
        #pragma unroll
        for (int mt = 0; mt < 4; mt++) {
            #pragma unroll
            for (int nt = 0; nt < 4; nt++) {
                int kl = wn * 32 + nt * 8 + t * 2;
                float2 bv = *(const float2*)&bias[bn + kl];
                float v0 = acc[mt][nt][0] + bv.x;
                float v1 = acc[mt][nt][1] + bv.y;
                float v2 = acc[mt][nt][2] + bv.x;
                float v3 = acc[mt][nt][3] + bv.y;
                v0 = 0.5f * v0 * (1.0f + erff(v0 * 0.70710678118654752f));
                v1 = 0.5f * v1 * (1.0f + erff(v1 * 0.70710678118654752f));
                v2 = 0.5f * v2 * (1.0f + erff(v2 * 0.70710678118654752f));
                v3 = 0.5f * v3 * (1.0f + erff(v3 * 0.70710678118654752f));
                int mtl = wm * 4 + mt;
                int ktl = kl >> 4;
                int tt = (kl & 7) >> 1;
                int rk = (kl >> 3) & 1;
                int baseI = ((mtl * 8 + ktl) * 32 + g * 4 + tt) * 4;
                sh[baseI + 2 * rk] = packh2(v0, v1);
                sh[baseI + 1 + 2 * rk] = packh2(v2, v3);
            }
        }
        __syncthreads();
        const int ktO = Nt >> 4;
        #pragma unroll
        for (int q = 0; q < 8; q++) {
            int i = q * 256 + tid;             // 0..2047 uint4 slots
            int mtl = i >> 8, jj = i & 255;
            size_t gidx = (((size_t)(bm16 + mtl) * ktO + (bn >> 4)) * 128) + (size_t)jj * 4;
            *(uint4*)(OutHi + gidx) = ((const uint4*)sh)[i];
        }
    }
}

// ======================= fused flash attention (bf16 3-term, unchanged) =====
// grid (4 q-tiles, 8*NH). batch bb = blockIdx.y>>4 in 0..7 (x:0-3, y:4-7).
// KV batch = bb ^ kvxor. Output written as packed fp16 A-fragments.
#define FA_QH 0
#define FA_QL 16384
#define FA_KH 32768
#define FA_KL 49152
#define FA_VH 65536
#define FA_VL 81920
#define FA_SMEM 98304

__global__ void __launch_bounds__(256, 1) fattn_kernel(
    const float* __restrict__ NA, int kvxor,
    uint32_t* __restrict__ Ohi, const int* guard)
{
    if (guard && !guard[0]) return;
    extern __shared__ __align__(16) char smf[];
    const int tid = threadIdx.x, lane = tid & 31, warp = tid >> 5;
    const int g = lane >> 2, t = lane & 3;
    const int bh = blockIdx.y, b = bh >> 4, h = bh & 15;
    const int n0 = blockIdx.x * 128;
    const float* Qb = NA + (size_t)b * N_ * C_ + h * D_;
    const float* Kb = NA + (size_t)(b ^ kvxor) * N_ * C_ + h * D_;

    // ---- Q -> A-fragments (hi/lo), scaled by 1/8 ----
    {
        const int arow = tid >> 1, hf = tid & 1;
        const float* qp = Qb + (size_t)(n0 + arow) * C_ + hf * 32;
        const int mtile = arow >> 4, ag = arow & 7, arm = (arow >> 3) & 1;
        #pragma unroll
        for (int q4 = 0; q4 < 8; q4++) {
            float4 v = *(const float4*)(qp + q4 * 4);
            float xs[4] = {v.x * 0.125f, v.y * 0.125f, v.z * 0.125f, v.w * 0.125f};
            #pragma unroll
            for (int p = 0; p < 2; p++) {
                int d = hf * 32 + q4 * 4 + 2 * p;
                uint32_t ph, pl;
                split_pack(xs[2 * p], xs[2 * p + 1], ph, pl);
                int kt = d >> 4, kin = d & 15;
                int tt = (kin & 7) >> 1, rk = kin >> 3;
                uint32_t idx = (uint32_t)(((mtile * 4 + kt) * 32 + ag * 4 + tt) * 4 + (arm + 2 * rk));
                *(uint32_t*)(smf + FA_QH + idx * 4) = ph;
                *(uint32_t*)(smf + FA_QL + idx * 4) = pl;
            }
        }
    }
    __syncthreads();

    uint32_t qh[4][4], ql[4][4];
    #pragma unroll
    for (int kt = 0; kt < 4; kt++) {
        uint4 v = *(const uint4*)(smf + FA_QH + (size_t)(((warp * 4 + kt) * 32 + lane) * 4) * 4);
        qh[kt][0] = v.x; qh[kt][1] = v.y; qh[kt][2] = v.z; qh[kt][3] = v.w;
        uint4 w = *(const uint4*)(smf + FA_QL + (size_t)(((warp * 4 + kt) * 32 + lane) * 4) * 4);
        ql[kt][0] = w.x; ql[kt][1] = w.y; ql[kt][2] = w.z; ql[kt][3] = w.w;
    }

    float o[8][4] = {};
    float m0 = -1e30f, m1 = -1e30f, l0 = 0.f, l1 = 0.f;

    for (int ch = 0; ch < 4; ch++) {
        const int s0 = ch * 128;
        __syncthreads();
        // ---- K chunk -> B-frags ----
        {
            const int r = tid >> 1, hf = tid & 1;
            const float* kp = Kb + (size_t)(s0 + r) * C_ + hf * 32;
            const int ntile = r >> 3, kg = r & 7;
            #pragma unroll
            for (int q4 = 0; q4 < 8; q4++) {
                float4 v = *(const float4*)(kp + q4 * 4);
                float xs[4] = {v.x, v.y, v.z, v.w};
                #pragma unroll
                for (int p = 0; p < 2; p++) {
                    int d = hf * 32 + q4 * 4 + 2 * p;
                    uint32_t ph, pl;
                    split_pack(xs[2 * p], xs[2 * p + 1], ph, pl);
                    int kt = d >> 4;
                    int lanef = kg * 4 + ((d & 7) >> 1);
                    int reg = ((d & 15) >= 8) ? 1 : 0;
                    uint32_t idx = (uint32_t)(((ntile * 4 + kt) * 32 + lanef) * 2 + reg);
                    *(uint32_t*)(smf + FA_KH + idx * 4) = ph;
                    *(uint32_t*)(smf + FA_KL + idx * 4) = pl;
                }
            }
        }
        // ---- V chunk -> B-frags (n=d, k=s) ----
        {
            const int sp = tid & 63, dq = tid >> 6;
            const float* vp = Kb + (size_t)(s0 + 2 * sp) * C_ + dq * 16;
            #pragma unroll
            for (int q4 = 0; q4 < 4; q4++) {
                float4 a = *(const float4*)(vp + q4 * 4);
                float4 c = *(const float4*)(vp + C_ + q4 * 4);
                float as[4] = {a.x, a.y, a.z, a.w};
                float cs[4] = {c.x, c.y, c.z, c.w};
                #pragma unroll
                for (int e = 0; e < 4; e++) {
                    int d = dq * 16 + q4 * 4 + e;
                    uint32_t ph, pl;
                    split_pack(as[e], cs[e], ph, pl);
                    int dnt = d >> 3, skt = sp >> 3;
                    int lanef = (d & 7) * 4 + (sp & 3);
                    int reg = (sp >> 2) & 1;
                    uint32_t idx = (uint32_t)(((dnt * 8 + skt) * 32 + lanef) * 2 + reg);
                    *(uint32_t*)(smf + FA_VH + idx * 4) = ph;
                    *(uint32_t*)(smf + FA_VL + idx * 4) = pl;
                }
            }
        }
        __syncthreads();

        // ---- S = Q @ K^T (3-term) ----
        float s[16][4];
        #pragma unroll
        for (int nt = 0; nt < 16; nt++) { s[nt][0] = s[nt][1] = s[nt][2] = s[nt][3] = 0.f; }
        #pragma unroll
        for (int nt = 0; nt < 16; nt++) {
            #pragma unroll
            for (int kt = 0; kt < 4; kt++) {
                uint32_t kh[2], kl[2];
                uint2 a = *(const uint2*)(smf + FA_KH + (size_t)(((nt * 4 + kt) * 32 + lane) * 2) * 4);
                kh[0] = a.x; kh[1] = a.y;
                uint2 c = *(const uint2*)(smf + FA_KL + (size_t)(((nt * 4 + kt) * 32 + lane) * 2) * 4);
                kl[0] = c.x; kl[1] = c.y;
                mma_bf16(s[nt], qh[kt], kh);
                mma_bf16(s[nt], qh[kt], kl);
                mma_bf16(s[nt], ql[kt], kh);
            }
        }

        // ---- online softmax ----
        float cm0 = -1e30f, cm1 = -1e30f;
        #pragma unroll
        for (int nt = 0; nt < 16; nt++) {
            cm0 = fmaxf(cm0, fmaxf(s[nt][0], s[nt][1]));
            cm1 = fmaxf(cm1, fmaxf(s[nt][2], s[nt][3]));
        }
        cm0 = fmaxf(cm0, __shfl_xor_sync(0xffffffffu, cm0, 1));
        cm0 = fmaxf(cm0, __shfl_xor_sync(0xffffffffu, cm0, 2));
        cm1 = fmaxf(cm1, __shfl_xor_sync(0xffffffffu, cm1, 1));
        cm1 = fmaxf(cm1, __shfl_xor_sync(0xffffffffu, cm1, 2));
        float nm0 = fmaxf(m0, cm0), nm1 = fmaxf(m1, cm1);
        float al0 = fast_exp(m0 - nm0), al1 = fast_exp(m1 - nm1);
        m0 = nm0; m1 = nm1;
        #pragma unroll
        for (int dnt = 0; dnt < 8; dnt++) {
            o[dnt][0] *= al0; o[dnt][1] *= al0;
            o[dnt][2] *= al1; o[dnt][3] *= al1;
        }
        float ls0 = 0.f, ls1 = 0.f;

        #pragma unroll
        for (int kt = 0; kt < 8; kt++) {
            float p00 = fast_exp(s[2 * kt][0] - m0);
            float p01 = fast_exp(s[2 * kt][1] - m0);
            float p02 = fast_exp(s[2 * kt][2] - m1);
            float p03 = fast_exp(s[2 * kt][3] - m1);
            float p10 = fast_exp(s[2 * kt + 1][0] - m0);
            float p11 = fast_exp(s[2 * kt + 1][1] - m0);
            float p12 = fast_exp(s[2 * kt + 1][2] - m1);
            float p13 = fast_exp(s[2 * kt + 1][3] - m1);
            ls0 += p00 + p01 + p10 + p11;
            ls1 += p02 + p03 + p12 + p13;
            uint32_t ph[4], pl[4];
            split_pack(p00, p01, ph[0], pl[0]);
            split_pack(p02, p03, ph[1], pl[1]);
            split_pack(p10, p11, ph[2], pl[2]);
            split_pack(p12, p13, ph[3], pl[3]);
            #pragma unroll
            for (int dnt = 0; dnt < 8; dnt++) {
                uint32_t vh[2], vl[2];
                uint2 a = *(const uint2*)(smf + FA_VH + (size_t)(((dnt * 8 + kt) * 32 + lane) * 2) * 4);
                vh[0] = a.x; vh[1] = a.y;
                uint2 c = *(const uint2*)(smf + FA_VL + (size_t)(((dnt * 8 + kt) * 32 + lane) * 2) * 4);
                vl[0] = c.x; vl[1] = c.y;
                mma_bf16(o[dnt], ph, vh);
                mma_bf16(o[dnt], ph, vl);
                mma_bf16(o[dnt], pl, vh);
            }
        }
        ls0 += __shfl_xor_sync(0xffffffffu, ls0, 1);
        ls0 += __shfl_xor_sync(0xffffffffu, ls0, 2);
        ls1 += __shfl_xor_sync(0xffffffffu, ls1, 1);
        ls1 += __shfl_xor_sync(0xffffffffu, ls1, 2);
        l0 = l0 * al0 + ls0;
        l1 = l1 * al1 + ls1;
    }

    // ---- packed fp16 epilogue ----
    __syncthreads();
    uint32_t* sh = (uint32_t*)(smf + FA_KH);   // 4096 u32 (16KB)
    float inv0 = 1.0f / l0, inv1 = 1.0f / l1;
    #pragma unroll
    for (int dnt = 0; dnt < 8; dnt++) {
        int kl_ = dnt * 8 + 2 * t;
        int ktl = kl_ >> 4;
        int rk = dnt & 1;
        int baseI = ((warp * 4 + ktl) * 32 + lane) * 4;
        sh[baseI + 2 * rk] = packh2(o[dnt][0] * inv0, o[dnt][1] * inv0);
        sh[baseI + 1 + 2 * rk] = packh2(o[dnt][2] * inv1, o[dnt][3] * inv1);
    }
    __syncthreads();
    #pragma unroll
    for (int q = 0; q < 4; q++) {
        int i = q * 256 + tid;
        int mtl = i >> 7, jj = i & 127;
        size_t gidx = (((size_t)(b * 32 + blockIdx.x * 8 + mtl) * 64) + h * 4) * 128 + (size_t)jj * 4;
        *(uint4*)(Ohi + gidx) = ((const uint4*)sh)[i];
    }
}

// ======================= host orchestration =======================
struct Weights {
    const float *n1g, *n1b, *n2g, *n2b, *pw, *pb, *w1, *b1, *w2, *b2;
};
struct Bufs {
    float *zb, *na;
    uint32_t *obh, *n2h, *hbh;
    uint32_t *pwh, *w1h, *w2h;
};

// One full transformer block over the batched 4096-row stream.
static void block_batched(float* resbuf, float* outbuf, int kvxor,
                          const Bufs& B, const Weights& W, const int* guard) {
    ln_kernel<<<R2_, 256>>>(resbuf, B.na, W.n1g, W.n1b, guard);
    fattn_kernel<<<dim3(4, 8 * NH_), 256, FA_SMEM>>>(B.na, kvxor, B.obh, guard);
    gemm_mma<1><<<dim3(C_ / 128, R2_ / 128), 256, GM_SMEM>>>(
        B.obh, B.pwh, outbuf, W.pb, resbuf, nullptr, R2_, C_, C_, guard);
    lnp_kernel<<<R2_ / 16, 256, 32768>>>(outbuf, B.n2h, W.n2g, W.n2b, guard);
    gemm_mma<2><<<dim3(HID_ / 128, R2_ / 128), 256, GM_SMEM>>>(
        B.n2h, B.w1h, nullptr, W.b1, nullptr, B.hbh, R2_, HID_, C_, guard);
    gemm_mma<1><<<dim3(C_ / 128, R2_ / 128), 256, GM_SMEM>>>(
        B.hbh, B.w2h, outbuf, W.b2, outbuf, nullptr, R2_, C_, HID_, guard);
}

extern "C" void kernel_launch(void* const* d_in, const int* in_sizes, int n_in,
                              void* d_out, int out_size) {
    const float* x   = (const float*)d_in[0];
    const float* y   = (const float*)d_in[1];
    Weights W;
    W.n1g = (const float*)d_in[2];  W.n1b = (const float*)d_in[3];
    W.n2g = (const float*)d_in[4];  W.n2b = (const float*)d_in[5];
    W.pw  = (const float*)d_in[6];  W.pb  = (const float*)d_in[7];
    W.w1  = (const float*)d_in[8];  W.b1  = (const float*)d_in[9];
    W.w2  = (const float*)d_in[10]; W.b2  = (const float*)d_in[11];
    const int* flag = (const int*)d_in[12];
    float* out = (float*)d_out;    // 4096 x 1024 = concat(x1, y1)

    Bufs B;
    cudaGetSymbolAddress((void**)&B.zb, g_zb);
    cudaGetSymbolAddress((void**)&B.na, g_na);
    cudaGetSymbolAddress((void**)&B.obh, g_obh);
    cudaGetSymbolAddress((void**)&B.n2h, g_n2h);
    cudaGetSymbolAddress((void**)&B.hbh, g_hbh);
    cudaGetSymbolAddress((void**)&B.pwh, g_pwh);
    cudaGetSymbolAddress((void**)&B.w1h, g_w1h);
    cudaGetSymbolAddress((void**)&B.w2h, g_w2h);

    cudaFuncSetAttribute(gemm_mma<1>, cudaFuncAttributeMaxDynamicSharedMemorySize, GM_SMEM);
    cudaFuncSetAttribute(gemm_mma<2>, cudaFuncAttributeMaxDynamicSharedMemorySize, GM_SMEM);
    cudaFuncSetAttribute(fattn_kernel, cudaFuncAttributeMaxDynamicSharedMemorySize, FA_SMEM);
    cudaFuncSetAttribute(lnp_kernel, cudaFuncAttributeMaxDynamicSharedMemorySize, 32768);

    // weight prep (runs every launch; ~15us)
    pack_weight<<<512, 256>>>(W.pw, B.pwh, C_, C_);
    pack_weight<<<512, 256>>>(W.w1, B.w1h, C_, HID_);
    pack_weight<<<512, 256>>>(W.w2, B.w2h, HID_, C_);

    const size_t bytes = (size_t)R_ * C_ * sizeof(float);
    cudaMemcpyAsync(B.zb, x, bytes, cudaMemcpyDeviceToDevice);
    cudaMemcpyAsync(B.zb + (size_t)R_ * C_, y, bytes, cudaMemcpyDeviceToDevice);

    // x and y self-chains batched as 8 "batches" (x:0-3, y:4-7). Only the
    // FINAL iteration's cross block is live: 4 gated self blocks, then one
    // cross block (kv from opposite half).
    for (int it = 0; it < 4; it++) {
        block_batched(B.zb, B.zb, 0, B, W, flag);
    }
    block_batched(B.zb, out, 4, B, W, nullptr);
}

// round 12
// speedup vs baseline: 2.2414x; 1.1440x over previous
#include <cuda_runtime.h>
#include <cuda_bf16.h>
#include <cuda_fp16.h>
#include <math.h>
#include <stdint.h>

// Problem dims (fixed by the dataset)
#define B_   4
#define N_   512
#define C_   1024
#define HID_ 4096
#define NH_  16
#define D_   64
#define R_   (B_*N_)     // 2048 rows per stream
#define R2_  (2*R_)      // 4096 rows: x-stream and y-stream batched
#define EPS_ 1e-5f

// ---------------- scratch (device globals: no allocation allowed) ----------
__device__ float g_zb[R2_*C_];    // concat(x, y) residual stream
__device__ float g_na[R2_*C_];    // ln1 out (fattn input)
// fp16-packed (A-fragment layout) activations
__device__ uint32_t g_obh[R2_*C_/2];    // fattn out -> proj A
__device__ uint32_t g_n2h[R2_*C_/2];    // ln2 out   -> fc1 A
__device__ uint32_t g_hbh[R2_*HID_/2];  // gelu out  -> fc2 A
// fp16 weights packed in mma.m16n8k16 B-fragment layout
__device__ uint32_t g_pwh[C_*C_/2];
__device__ uint32_t g_w1h[C_*HID_/2];
__device__ uint32_t g_w2h[HID_*C_/2];

// ======================= helpers =======================
#define CP_ASYNC16(sm, gp) \
    asm volatile("cp.async.cg.shared.global [%0], [%1], 16;" :: "r"(sm), "l"(gp))
#define CP_COMMIT() asm volatile("cp.async.commit_group;" ::: "memory")
#define CP_WAIT0()  asm volatile("cp.async.wait_group 0;" ::: "memory")
#define CP_WAIT1()  asm volatile("cp.async.wait_group 1;" ::: "memory")

__device__ __forceinline__ uint32_t smem_u32(const void* p) {
    uint32_t a;
    asm("{ .reg .u64 t; cvta.to.shared.u64 t, %1; cvt.u32.u64 %0, t; }" : "=r"(a) : "l"(p));
    return a;
}

// fp16 pair pack (low half = first element)
__device__ __forceinline__ uint32_t packh2(float a, float b) {
    __half2 h = __halves2half2(__float2half_rn(a), __float2half_rn(b));
    return *(uint32_t*)&h;
}

__device__ __forceinline__ void mma_f16(float* c, const uint32_t* a, const uint32_t* b) {
    asm volatile(
        "mma.sync.aligned.m16n8k16.row.col.f32.f16.f16.f32 "
        "{%0,%1,%2,%3}, {%4,%5,%6,%7}, {%8,%9}, {%0,%1,%2,%3};"
        : "+f"(c[0]), "+f"(c[1]), "+f"(c[2]), "+f"(c[3])
        : "r"(a[0]), "r"(a[1]), "r"(a[2]), "r"(a[3]), "r"(b[0]), "r"(b[1]));
}

__device__ __forceinline__ float fast_exp(float x) {
    float tt = fmaxf(x * 1.4426950408889634f, -126.0f);
    float fi = floorf(tt);
    float f = tt - fi;
    float p = 0.0013333558f;
    p = fmaf(p, f, 0.0096181291f);
    p = fmaf(p, f, 0.0555041087f);
    p = fmaf(p, f, 0.2402265070f);
    p = fmaf(p, f, 0.6931471806f);
    p = fmaf(p, f, 1.0f);
    return p * __int_as_float((__float2int_rn(fi) + 127) << 23);
}

// ======================= LayerNorm (raw out, for ln1) =======================
__global__ void ln_kernel(const float* __restrict__ in, float* __restrict__ out,
                          const float* __restrict__ gm, const float* __restrict__ bt,
                          const int* guard) {
    if (guard && !guard[0]) return;
    int row = blockIdx.x;
    const float* x = in + (size_t)row * C_;
    float* y = out + (size_t)row * C_;
    float s = 0.f, ss = 0.f;
    for (int i = threadIdx.x; i < C_; i += 256) {
        float v = x[i];
        s += v; ss += v * v;
    }
    __shared__ float red[16];
    for (int o = 16; o; o >>= 1) {
        s  += __shfl_down_sync(0xffffffffu, s, o);
        ss += __shfl_down_sync(0xffffffffu, ss, o);
    }
    int wid = threadIdx.x >> 5, lid = threadIdx.x & 31;
    if (!lid) { red[wid] = s; red[wid + 8] = ss; }
    __syncthreads();
    float mean, rstd;
    {
        float a = 0.f, c2 = 0.f;
        #pragma unroll
        for (int i = 0; i < 8; i++) { a += red[i]; c2 += red[i + 8]; }
        mean = a * (1.0f / C_);
        float var = c2 * (1.0f / C_) - mean * mean;
        rstd = rsqrtf(var + EPS_);
    }
    for (int i = threadIdx.x; i < C_; i += 256) {
        y[i] = (x[i] - mean) * rstd * gm[i] + bt[i];
    }
}

// ============ LayerNorm -> packed fp16 A-fragments (for ln2 -> fc1) =========
__global__ void __launch_bounds__(256) lnp_kernel(
    const float* __restrict__ in, uint32_t* __restrict__ outH,
    const float* __restrict__ gm, const float* __restrict__ bt,
    const int* guard)
{
    if (guard && !guard[0]) return;
    extern __shared__ __align__(16) char sml[];
    uint32_t* sh = (uint32_t*)sml;              // 8192 u32 (32KB)
    const int w = threadIdx.x >> 5, lane = threadIdx.x & 31;

    #pragma unroll
    for (int rr = 0; rr < 2; rr++) {
        const int row = blockIdx.x * 16 + w * 2 + rr;
        const float* x = in + (size_t)row * C_;
        float4 v[8];
        float s = 0.f, ss = 0.f;
        #pragma unroll
        for (int i = 0; i < 8; i++) {
            v[i] = *(const float4*)(x + i * 128 + lane * 4);
            s += v[i].x + v[i].y + v[i].z + v[i].w;
            ss += v[i].x * v[i].x + v[i].y * v[i].y + v[i].z * v[i].z + v[i].w * v[i].w;
        }
        #pragma unroll
        for (int o = 16; o; o >>= 1) {
            s  += __shfl_xor_sync(0xffffffffu, s, o);
            ss += __shfl_xor_sync(0xffffffffu, ss, o);
        }
        float mean = s * (1.0f / C_);
        float rstd = rsqrtf(ss * (1.0f / C_) - mean * mean + EPS_);
        const int ag = row & 7, m8 = (row >> 3) & 1;
        const int kin = (lane & 3) * 4;
        const int tt0 = (kin & 7) >> 1, rk = kin >> 3;
        #pragma unroll
        for (int i = 0; i < 8; i++) {
            int c = i * 128 + lane * 4;
            float4 gv = *(const float4*)(gm + c);
            float4 bv = *(const float4*)(bt + c);
            float n0 = (v[i].x - mean) * rstd * gv.x + bv.x;
            float n1 = (v[i].y - mean) * rstd * gv.y + bv.y;
            float n2 = (v[i].z - mean) * rstd * gv.z + bv.z;
            float n3 = (v[i].w - mean) * rstd * gv.w + bv.w;
            int kt = c >> 4;
            int r = m8 + 2 * rk;
            sh[(kt * 32 + ag * 4 + tt0) * 4 + r] = packh2(n0, n1);
            sh[(kt * 32 + ag * 4 + tt0 + 1) * 4 + r] = packh2(n2, n3);
        }
    }
    __syncthreads();
    size_t gbase = (size_t)blockIdx.x * 8192;
    #pragma unroll
    for (int q = 0; q < 8; q++) {
        int i = q * 256 + threadIdx.x;
        *(uint4*)(outH + gbase + (size_t)i * 4) = ((const uint4*)sh)[i];
    }
}

// ========== weight prep: fp16 pack into B-fragment layout =========
__global__ void pack_weight(const float* __restrict__ W, uint32_t* __restrict__ hiP,
                            int K, int N) {
    int warp = threadIdx.x >> 5, lane = threadIdx.x & 31;
    int g = lane >> 2, t = lane & 3;
    int ktiles = K >> 4;
    int tiles = (N >> 3) * ktiles;
    for (int tile = blockIdx.x * 8 + warp; tile < tiles; tile += gridDim.x * 8) {
        int ntg = tile / ktiles, ksg = tile % ktiles;
        int n = ntg * 8 + g;
        #pragma unroll
        for (int reg = 0; reg < 2; reg++) {
            int k = ksg * 16 + 2 * t + reg * 8;
            float x0 = W[(size_t)k * N + n];
            float x1 = W[(size_t)(k + 1) * N + n];
            hiP[((size_t)tile * 32 + lane) * 2 + reg] = packh2(x0, x1);
        }
    }
}

// ======================= fp16 mma GEMM (packed A + packed B) ==========
// 128x128 CTA tile, K-step 32, 3-stage cp.async pipeline, 8 warps (2M x 4N).
// Stage (16KB): A[0,8K) B[8K,16K).
#define GM_STAGE 16384
#define GM_SMEM  (3 * GM_STAGE)

template <int EPI>
__global__ void __launch_bounds__(256) gemm_mma(
    const uint32_t* __restrict__ AP, const uint32_t* __restrict__ BP,
    float* __restrict__ Cout, const float* __restrict__ bias,
    const float* __restrict__ res, uint32_t* __restrict__ OutHi,
    int M, int Nt, int K, const int* guard)
{
    if (guard && !guard[0]) return;
    extern __shared__ __align__(16) char smc[];
    const int tid = threadIdx.x;
    const int warp = tid >> 5, lane = tid & 31;
    const int g = lane >> 2, t = lane & 3;
    const int wm = warp & 1, wn = warp >> 1;
    const int bm = blockIdx.y * 128, bn = blockIdx.x * 128;
    const uint32_t sb = smem_u32(smc);

    const int NIT = K >> 5;
    const int ktiles = K >> 4;
    const int bm16 = bm >> 4, bn8 = bn >> 3;

    auto cpA = [&](int stage, int it) {
        uint32_t dstb = sb + stage * GM_STAGE;
        int kt0 = it * 2;
        #pragma unroll
        for (int q = 0; q < 2; q++) {
            int chunk = q * 256 + tid;        // 0..511
            int mtk = chunk >> 5, j = chunk & 31;
            int mtl = mtk >> 1, ktl = mtk & 1;
            size_t gidx = (((size_t)(bm16 + mtl) * ktiles + kt0 + ktl) * 32 + j) * 4;
            CP_ASYNC16(dstb + (uint32_t)(mtk * 512 + j * 16), AP + gidx);
        }
    };
    auto cpB = [&](int stage, int it) {
        uint32_t dstb = sb + stage * GM_STAGE + 8192u;
        int ksg0 = it * 2;
        #pragma unroll
        for (int q = 0; q < 2; q++) {
            int i = q * 256 + tid;            // 0..511
            int nt = i >> 5, j = i & 31;
            size_t srcoff = (((size_t)(bn8 + nt) * ktiles + ksg0) * 64 + (size_t)j * 4);
            CP_ASYNC16(dstb + (uint32_t)(nt * 512 + j * 16), BP + srcoff);
        }
    };

    float acc[4][4][4] = {};

    auto compute = [&](int stage) {
        char* base = smc + stage * GM_STAGE;
        #pragma unroll
        for (int ks = 0; ks < 2; ks++) {
            uint32_t ah[4][4], bh[4][2];
            #pragma unroll
            for (int mt = 0; mt < 4; mt++) {
                uint32_t off = (uint32_t)(((wm * 4 + mt) * 2 + ks) * 32 + lane) * 16;
                uint4 v = *(const uint4*)(base + off);
                ah[mt][0] = v.x; ah[mt][1] = v.y; ah[mt][2] = v.z; ah[mt][3] = v.w;
            }
            #pragma unroll
            for (int nt = 0; nt < 4; nt++) {
                uint32_t off = 8192u + (uint32_t)(((wn * 4 + nt) * 2 + ks) * 32 + lane) * 8;
                uint2 v = *(const uint2*)(base + off);
                bh[nt][0] = v.x; bh[nt][1] = v.y;
            }
            #pragma unroll
            for (int mt = 0; mt < 4; mt++)
                #pragma unroll
                for (int nt = 0; nt < 4; nt++)
                    mma_f16(acc[mt][nt], ah[mt], bh[nt]);
        }
    };

    cpA(0, 0); cpB(0, 0); CP_COMMIT();
    cpA(1, 1); cpB(1, 1); CP_COMMIT();

    int st = 0;
    for (int it = 0; it < NIT; it++) {
        if (it + 1 < NIT) { CP_WAIT1(); } else { CP_WAIT0(); }
        __syncthreads();
        if (it + 2 < NIT) {
            int ns = st + 2; if (ns >= 3) ns -= 3;
            cpA(ns, it + 2); cpB(ns, it + 2); CP_COMMIT();
        }
        compute(st);
        if (++st == 3) st = 0;
    }
    __syncthreads();

    if (EPI == 1) {
        #pragma unroll
        for (int mt = 0; mt < 4; mt++) {
            #pragma unroll
            for (int nt = 0; nt < 4; nt++) {
                int row0 = bm + wm * 64 + mt * 16 + g;
                int col = bn + wn * 32 + nt * 8 + t * 2;
                float2 bv = *(const float2*)&bias[col];
                float v0 = acc[mt][nt][0] + bv.x;
                float v1 = acc[mt][nt][1] + bv.y;
                float v2 = acc[mt][nt][2] + bv.x;
                float v3 = acc[mt][nt][3] + bv.y;
                size_t i0 = (size_t)row0 * Nt + col;
                size_t i1 = (size_t)(row0 + 8) * Nt + col;
                float2 r0 = *(const float2*)&res[i0];
                float2 r1 = *(const float2*)&res[i1];
                *(float2*)&Cout[i0] = make_float2(v0 + r0.x, v1 + r0.y);
                *(float2*)&Cout[i1] = make_float2(v2 + r1.x, v3 + r1.y);
            }
        }
    } else {
        // GELU -> packed fp16 A-fragments (32KB staged in smem)
        uint32_t* sh = (uint32_t*)smc;
        #pragma unroll
        for (int mt = 0; mt < 4; mt++) {
            #pragma unroll
            for (int nt = 0; nt < 4; nt++) {
                int kl = wn * 32 + nt * 8 + t * 2;
                float2 bv = *(const float2*)&bias[bn + kl];
                float v0 = acc[mt][nt][0] + bv.x;
                float v1 = acc[mt][nt][1] + bv.y;
                float v2 = acc[mt][nt][2] + bv.x;
                float v3 = acc[mt][nt][3] + bv.y;
                v0 = 0.5f * v0 * (1.0f + erff(v0 * 0.70710678118654752f));
                v1 = 0.5f * v1 * (1.0f + erff(v1 * 0.70710678118654752f));
                v2 = 0.5f * v2 * (1.0f + erff(v2 * 0.70710678118654752f));
                v3 = 0.5f * v3 * (1.0f + erff(v3 * 0.70710678118654752f));
                int mtl = wm * 4 + mt;
                int ktl = kl >> 4;
                int tt = (kl & 7) >> 1;
                int rk = (kl >> 3) & 1;
                int baseI = ((mtl * 8 + ktl) * 32 + g * 4 + tt) * 4;
                sh[baseI + 2 * rk] = packh2(v0, v1);
                sh[baseI + 1 + 2 * rk] = packh2(v2, v3);
            }
        }
        __syncthreads();
        const int ktO = Nt >> 4;
        #pragma unroll
        for (int q = 0; q < 8; q++) {
            int i = q * 256 + tid;             // 0..2047 uint4 slots
            int mtl = i >> 8, jj = i & 255;
            size_t gidx = (((size_t)(bm16 + mtl) * ktO + (bn >> 4)) * 128) + (size_t)jj * 4;
            *(uint4*)(OutHi + gidx) = ((const uint4*)sh)[i];
        }
    }
}

// ======================= fused flash attention (fp16 single-term) ===========
// grid (4 q-tiles, 8*NH). batch bb = blockIdx.y>>4 in 0..7 (x:0-3, y:4-7).
// KV batch = bb ^ kvxor. Output written as packed fp16 A-fragments.
#define FA_QH 0
#define FA_KH 16384
#define FA_VH 32768
#define FA_SMEM 49152

__global__ void __launch_bounds__(256, 1) fattn_kernel(
    const float* __restrict__ NA, int kvxor,
    uint32_t* __restrict__ Ohi, const int* guard)
{
    if (guard && !guard[0]) return;
    extern __shared__ __align__(16) char smf[];
    const int tid = threadIdx.x, lane = tid & 31, warp = tid >> 5;
    const int g = lane >> 2, t = lane & 3;
    const int bh = blockIdx.y, b = bh >> 4, h = bh & 15;
    const int n0 = blockIdx.x * 128;
    const float* Qb = NA + (size_t)b * N_ * C_ + h * D_;
    const float* Kb = NA + (size_t)(b ^ kvxor) * N_ * C_ + h * D_;

    // ---- Q -> fp16 A-fragments, scaled by 1/8 ----
    {
        const int arow = tid >> 1, hf = tid & 1;
        const float* qp = Qb + (size_t)(n0 + arow) * C_ + hf * 32;
        const int mtile = arow >> 4, ag = arow & 7, arm = (arow >> 3) & 1;
        #pragma unroll
        for (int q4 = 0; q4 < 8; q4++) {
            float4 v = *(const float4*)(qp + q4 * 4);
            float xs[4] = {v.x * 0.125f, v.y * 0.125f, v.z * 0.125f, v.w * 0.125f};
            #pragma unroll
            for (int p = 0; p < 2; p++) {
                int d = hf * 32 + q4 * 4 + 2 * p;
                int kt = d >> 4, kin = d & 15;
                int tt = (kin & 7) >> 1, rk = kin >> 3;
                uint32_t idx = (uint32_t)(((mtile * 4 + kt) * 32 + ag * 4 + tt) * 4 + (arm + 2 * rk));
                *(uint32_t*)(smf + FA_QH + idx * 4) = packh2(xs[2 * p], xs[2 * p + 1]);
            }
        }
    }
    __syncthreads();

    uint32_t qh[4][4];
    #pragma unroll
    for (int kt = 0; kt < 4; kt++) {
        uint4 v = *(const uint4*)(smf + FA_QH + (size_t)(((warp * 4 + kt) * 32 + lane) * 4) * 4);
        qh[kt][0] = v.x; qh[kt][1] = v.y; qh[kt][2] = v.z; qh[kt][3] = v.w;
    }

    float o[8][4] = {};
    float m0 = -1e30f, m1 = -1e30f, l0 = 0.f, l1 = 0.f;

    for (int ch = 0; ch < 4; ch++) {
        const int s0 = ch * 128;
        __syncthreads();
        // ---- K chunk -> fp16 B-frags ----
        {
            const int r = tid >> 1, hf = tid & 1;
            const float* kp = Kb + (size_t)(s0 + r) * C_ + hf * 32;
            const int ntile = r >> 3, kg = r & 7;
            #pragma unroll
            for (int q4 = 0; q4 < 8; q4++) {
                float4 v = *(const float4*)(kp + q4 * 4);
                float xs[4] = {v.x, v.y, v.z, v.w};
                #pragma unroll
                for (int p = 0; p < 2; p++) {
                    int d = hf * 32 + q4 * 4 + 2 * p;
                    int kt = d >> 4;
                    int lanef = kg * 4 + ((d & 7) >> 1);
                    int reg = ((d & 15) >= 8) ? 1 : 0;
                    uint32_t idx = (uint32_t)(((ntile * 4 + kt) * 32 + lanef) * 2 + reg);
                    *(uint32_t*)(smf + FA_KH + idx * 4) = packh2(xs[2 * p], xs[2 * p + 1]);
                }
            }
        }
        // ---- V chunk -> fp16 B-frags (n=d, k=s) ----
        {
            const int sp = tid & 63, dq = tid >> 6;
            const float* vp = Kb + (size_t)(s0 + 2 * sp) * C_ + dq * 16;
            #pragma unroll
            for (int q4 = 0; q4 < 4; q4++) {
                float4 a = *(const float4*)(vp + q4 * 4);
                float4 c = *(const float4*)(vp + C_ + q4 * 4);
                float as[4] = {a.x, a.y, a.z, a.w};
                float cs[4] = {c.x, c.y, c.z, c.w};
                #pragma unroll
                for (int e = 0; e < 4; e++) {
                    int d = dq * 16 + q4 * 4 + e;
                    int dnt = d >> 3, skt = sp >> 3;
                    int lanef = (d & 7) * 4 + (sp & 3);
                    int reg = (sp >> 2) & 1;
                    uint32_t idx = (uint32_t)(((dnt * 8 + skt) * 32 + lanef) * 2 + reg);
                    *(uint32_t*)(smf + FA_VH + idx * 4) = packh2(as[e], cs[e]);
                }
            }
        }
        __syncthreads();

        // ---- S = Q @ K^T (fp16) ----
        float s[16][4];
        #pragma unroll
        for (int nt = 0; nt < 16; nt++) { s[nt][0] = s[nt][1] = s[nt][2] = s[nt][3] = 0.f; }
        #pragma unroll
        for (int nt = 0; nt < 16; nt++) {
            #pragma unroll
            for (int kt = 0; kt < 4; kt++) {
                uint32_t kh[2];
                uint2 a = *(const uint2*)(smf + FA_KH + (size_t)(((nt * 4 + kt) * 32 + lane) * 2) * 4);
                kh[0] = a.x; kh[1] = a.y;
                mma_f16(s[nt], qh[kt], kh);
            }
        }

        // ---- online softmax ----
        float cm0 = -1e30f, cm1 = -1e30f;
        #pragma unroll
        for (int nt = 0; nt < 16; nt++) {
            cm0 = fmaxf(cm0, fmaxf(s[nt][0], s[nt][1]));
            cm1 = fmaxf(cm1, fmaxf(s[nt][2], s[nt][3]));
        }
        cm0 = fmaxf(cm0, __shfl_xor_sync(0xffffffffu, cm0, 1));
        cm0 = fmaxf(cm0, __shfl_xor_sync(0xffffffffu, cm0, 2));
        cm1 = fmaxf(cm1, __shfl_xor_sync(0xffffffffu, cm1, 1));
        cm1 = fmaxf(cm1, __shfl_xor_sync(0xffffffffu, cm1, 2));
        float nm0 = fmaxf(m0, cm0), nm1 = fmaxf(m1, cm1);
        float al0 = fast_exp(m0 - nm0), al1 = fast_exp(m1 - nm1);
        m0 = nm0; m1 = nm1;
        #pragma unroll
        for (int dnt = 0; dnt < 8; dnt++) {
            o[dnt][0] *= al0; o[dnt][1] *= al0;
            o[dnt][2] *= al1; o[dnt][3] *= al1;
        }
        float ls0 = 0.f, ls1 = 0.f;

        // ---- P = exp(S - m) (fp16 frags); PV mma ----
        #pragma unroll
        for (int kt = 0; kt < 8; kt++) {
            float p00 = fast_exp(s[2 * kt][0] - m0);
            float p01 = fast_exp(s[2 * kt][1] - m0);
            float p02 = fast_exp(s[2 * kt][2] - m1);
            float p03 = fast_exp(s[2 * kt][3] - m1);
            float p10 = fast_exp(s[2 * kt + 1][0] - m0);
            float p11 = fast_exp(s[2 * kt + 1][1] - m0);
            float p12 = fast_exp(s[2 * kt + 1][2] - m1);
            float p13 = fast_exp(s[2 * kt + 1][3] - m1);
            ls0 += p00 + p01 + p10 + p11;
            ls1 += p02 + p03 + p12 + p13;
            uint32_t ph[4];
            ph[0] = packh2(p00, p01);
            ph[1] = packh2(p02, p03);
            ph[2] = packh2(p10, p11);
            ph[3] = packh2(p12, p13);
            #pragma unroll
            for (int dnt = 0; dnt < 8; dnt++) {
                uint32_t vh[2];
                uint2 a = *(const uint2*)(smf + FA_VH + (size_t)(((dnt * 8 + kt) * 32 + lane) * 2) * 4);
                vh[0] = a.x; vh[1] = a.y;
                mma_f16(o[dnt], ph, vh);
            }
        }
        ls0 += __shfl_xor_sync(0xffffffffu, ls0, 1);
        ls0 += __shfl_xor_sync(0xffffffffu, ls0, 2);
        ls1 += __shfl_xor_sync(0xffffffffu, ls1, 1);
        ls1 += __shfl_xor_sync(0xffffffffu, ls1, 2);
        l0 = l0 * al0 + ls0;
        l1 = l1 * al1 + ls1;
    }

    // ---- packed fp16 epilogue ----
    __syncthreads();
    uint32_t* sh = (uint32_t*)(smf + FA_KH);   // 4096 u32 (16KB)
    float inv0 = 1.0f / l0, inv1 = 1.0f / l1;
    #pragma unroll
    for (int dnt = 0; dnt < 8; dnt++) {
        int kl_ = dnt * 8 + 2 * t;
        int ktl = kl_ >> 4;
        int rk = dnt & 1;
        int baseI = ((warp * 4 + ktl) * 32 + lane) * 4;
        sh[baseI + 2 * rk] = packh2(o[dnt][0] * inv0, o[dnt][1] * inv0);
        sh[baseI + 1 + 2 * rk] = packh2(o[dnt][2] * inv1, o[dnt][3] * inv1);
    }
    __syncthreads();
    #pragma unroll
    for (int q = 0; q < 4; q++) {
        int i = q * 256 + tid;
        int mtl = i >> 7, jj = i & 127;
        size_t gidx = (((size_t)(b * 32 + blockIdx.x * 8 + mtl) * 64) + h * 4) * 128 + (size_t)jj * 4;
        *(uint4*)(Ohi + gidx) = ((const uint4*)sh)[i];
    }
}

// ======================= host orchestration =======================
struct Weights {
    const float *n1g, *n1b, *n2g, *n2b, *pw, *pb, *w1, *b1, *w2, *b2;
};
struct Bufs {
    float *zb, *na;
    uint32_t *obh, *n2h, *hbh;
    uint32_t *pwh, *w1h, *w2h;
};

// One full transformer block over the batched 4096-row stream.
static void block_batched(float* resbuf, float* outbuf, int kvxor,
                          const Bufs& B, const Weights& W, const int* guard) {
    ln_kernel<<<R2_, 256>>>(resbuf, B.na, W.n1g, W.n1b, guard);
    fattn_kernel<<<dim3(4, 8 * NH_), 256, FA_SMEM>>>(B.na, kvxor, B.obh, guard);
    gemm_mma<1><<<dim3(C_ / 128, R2_ / 128), 256, GM_SMEM>>>(
        B.obh, B.pwh, outbuf, W.pb, resbuf, nullptr, R2_, C_, C_, guard);
    lnp_kernel<<<R2_ / 16, 256, 32768>>>(outbuf, B.n2h, W.n2g, W.n2b, guard);
    gemm_mma<2><<<dim3(HID_ / 128, R2_ / 128), 256, GM_SMEM>>>(
        B.n2h, B.w1h, nullptr, W.b1, nullptr, B.hbh, R2_, HID_, C_, guard);
    gemm_mma<1><<<dim3(C_ / 128, R2_ / 128), 256, GM_SMEM>>>(
        B.hbh, B.w2h, outbuf, W.b2, outbuf, nullptr, R2_, C_, HID_, guard);
}

extern "C" void kernel_launch(void* const* d_in, const int* in_sizes, int n_in,
                              void* d_out, int out_size) {
    const float* x   = (const float*)d_in[0];
    const float* y   = (const float*)d_in[1];
    Weights W;
    W.n1g = (const float*)d_in[2];  W.n1b = (const float*)d_in[3];
    W.n2g = (const float*)d_in[4];  W.n2b = (const float*)d_in[5];
    W.pw  = (const float*)d_in[6];  W.pb  = (const float*)d_in[7];
    W.w1  = (const float*)d_in[8];  W.b1  = (const float*)d_in[9];
    W.w2  = (const float*)d_in[10]; W.b2  = (const float*)d_in[11];
    const int* flag = (const int*)d_in[12];
    float* out = (float*)d_out;    // 4096 x 1024 = concat(x1, y1)

    Bufs B;
    cudaGetSymbolAddress((void**)&B.zb, g_zb);
    cudaGetSymbolAddress((void**)&B.na, g_na);
    cudaGetSymbolAddress((void**)&B.obh, g_obh);
    cudaGetSymbolAddress((void**)&B.n2h, g_n2h);
    cudaGetSymbolAddress((void**)&B.hbh, g_hbh);
    cudaGetSymbolAddress((void**)&B.pwh, g_pwh);
    cudaGetSymbolAddress((void**)&B.w1h, g_w1h);
    cudaGetSymbolAddress((void**)&B.w2h, g_w2h);

    cudaFuncSetAttribute(gemm_mma<1>, cudaFuncAttributeMaxDynamicSharedMemorySize, GM_SMEM);
    cudaFuncSetAttribute(gemm_mma<2>, cudaFuncAttributeMaxDynamicSharedMemorySize, GM_SMEM);
    cudaFuncSetAttribute(fattn_kernel, cudaFuncAttributeMaxDynamicSharedMemorySize, FA_SMEM);
    cudaFuncSetAttribute(lnp_kernel, cudaFuncAttributeMaxDynamicSharedMemorySize, 32768);

    // weight prep (runs every launch; ~15us)
    pack_weight<<<512, 256>>>(W.pw, B.pwh, C_, C_);
    pack_weight<<<512, 256>>>(W.w1, B.w1h, C_, HID_);
    pack_weight<<<512, 256>>>(W.w2, B.w2h, HID_, C_);

    const size_t bytes = (size_t)R_ * C_ * sizeof(float);
    cudaMemcpyAsync(B.zb, x, bytes, cudaMemcpyDeviceToDevice);
    cudaMemcpyAsync(B.zb + (size_t)R_ * C_, y, bytes, cudaMemcpyDeviceToDevice);

    // x and y self-chains batched as 8 "batches" (x:0-3, y:4-7). Only the
    // FINAL iteration's cross block is live: 4 gated self blocks, then one
    // cross block (kv from opposite half).
    for (int it = 0; it < 4; it++) {
        block_batched(B.zb, B.zb, 0, B, W, flag);
    }
    block_batched(B.zb, out, 4, B, W, nullptr);
}

// round 13
// speedup vs baseline: 2.3907x; 1.0666x over previous
#include <cuda_runtime.h>
#include <cuda_bf16.h>
#include <cuda_fp16.h>
#include <math.h>
#include <stdint.h>

// Problem dims (fixed by the dataset)
#define B_   4
#define N_   512
#define C_   1024
#define HID_ 4096
#define NH_  16
#define D_   64
#define R_   (B_*N_)     // 2048 rows per stream
#define R2_  (2*R_)      // 4096 rows: x-stream and y-stream batched
#define EPS_ 1e-5f

// ---------------- scratch (device globals: no allocation allowed) ----------
__device__ float g_zb[R2_*C_];    // concat(x, y) residual stream
__device__ float g_na[R2_*C_];    // ln1 out (fattn input)
// fp16-packed (A-fragment layout) activations
__device__ uint32_t g_obh[R2_*C_/2];    // fattn out -> proj A
__device__ uint32_t g_n2h[R2_*C_/2];    // ln2 out   -> fc1 A
__device__ uint32_t g_hbh[R2_*HID_/2];  // gelu out  -> fc2 A
// fp16 weights packed in mma.m16n8k16 B-fragment layout
__device__ uint32_t g_pwh[C_*C_/2];
__device__ uint32_t g_w1h[C_*HID_/2];
__device__ uint32_t g_w2h[HID_*C_/2];

// ======================= helpers =======================
#define CP_ASYNC16(sm, gp) \
    asm volatile("cp.async.cg.shared.global [%0], [%1], 16;" :: "r"(sm), "l"(gp))
#define CP_COMMIT() asm volatile("cp.async.commit_group;" ::: "memory")
#define CP_WAIT0()  asm volatile("cp.async.wait_group 0;" ::: "memory")
#define CP_WAIT1()  asm volatile("cp.async.wait_group 1;" ::: "memory")

__device__ __forceinline__ uint32_t smem_u32(const void* p) {
    uint32_t a;
    asm("{ .reg .u64 t; cvta.to.shared.u64 t, %1; cvt.u32.u64 %0, t; }" : "=r"(a) : "l"(p));
    return a;
}

// fp16 pair pack (low half = first element)
__device__ __forceinline__ uint32_t packh2(float a, float b) {
    __half2 h = __halves2half2(__float2half_rn(a), __float2half_rn(b));
    return *(uint32_t*)&h;
}

__device__ __forceinline__ void mma_f16(float* c, const uint32_t* a, const uint32_t* b) {
    asm volatile(
        "mma.sync.aligned.m16n8k16.row.col.f32.f16.f16.f32 "
        "{%0,%1,%2,%3}, {%4,%5,%6,%7}, {%8,%9}, {%0,%1,%2,%3};"
        : "+f"(c[0]), "+f"(c[1]), "+f"(c[2]), "+f"(c[3])
        : "r"(a[0]), "r"(a[1]), "r"(a[2]), "r"(a[3]), "r"(b[0]), "r"(b[1]));
}

__device__ __forceinline__ float fast_exp(float x) {
    float tt = fmaxf(x * 1.4426950408889634f, -126.0f);
    float fi = floorf(tt);
    float f = tt - fi;
    float p = 0.0013333558f;
    p = fmaf(p, f, 0.0096181291f);
    p = fmaf(p, f, 0.0555041087f);
    p = fmaf(p, f, 0.2402265070f);
    p = fmaf(p, f, 0.6931471806f);
    p = fmaf(p, f, 1.0f);
    return p * __int_as_float((__float2int_rn(fi) + 127) << 23);
}

// ======= LayerNorm (raw fp32 out, for ln1): 16 rows/block, float4 ==========
__global__ void __launch_bounds__(256) ln_kernel(
    const float* __restrict__ in, float* __restrict__ out,
    const float* __restrict__ gm, const float* __restrict__ bt,
    const int* guard) {
    if (guard && !guard[0]) return;
    const int w = threadIdx.x >> 5, lane = threadIdx.x & 31;
    #pragma unroll
    for (int rr = 0; rr < 2; rr++) {
        const int row = blockIdx.x * 16 + w * 2 + rr;
        const float* x = in + (size_t)row * C_;
        float* y = out + (size_t)row * C_;
        float4 v[8];
        float s = 0.f, ss = 0.f;
        #pragma unroll
        for (int i = 0; i < 8; i++) {
            v[i] = *(const float4*)(x + i * 128 + lane * 4);
            s += v[i].x + v[i].y + v[i].z + v[i].w;
            ss += v[i].x * v[i].x + v[i].y * v[i].y + v[i].z * v[i].z + v[i].w * v[i].w;
        }
        #pragma unroll
        for (int o = 16; o; o >>= 1) {
            s  += __shfl_xor_sync(0xffffffffu, s, o);
            ss += __shfl_xor_sync(0xffffffffu, ss, o);
        }
        float mean = s * (1.0f / C_);
        float rstd = rsqrtf(ss * (1.0f / C_) - mean * mean + EPS_);
        #pragma unroll
        for (int i = 0; i < 8; i++) {
            int c = i * 128 + lane * 4;
            float4 gv = *(const float4*)(gm + c);
            float4 bv = *(const float4*)(bt + c);
            float4 o4;
            o4.x = (v[i].x - mean) * rstd * gv.x + bv.x;
            o4.y = (v[i].y - mean) * rstd * gv.y + bv.y;
            o4.z = (v[i].z - mean) * rstd * gv.z + bv.z;
            o4.w = (v[i].w - mean) * rstd * gv.w + bv.w;
            *(float4*)(y + c) = o4;
        }
    }
}

// ============ LayerNorm -> packed fp16 A-fragments (for ln2 -> fc1) =========
__global__ void __launch_bounds__(256) lnp_kernel(
    const float* __restrict__ in, uint32_t* __restrict__ outH,
    const float* __restrict__ gm, const float* __restrict__ bt,
    const int* guard)
{
    if (guard && !guard[0]) return;
    extern __shared__ __align__(16) char sml[];
    uint32_t* sh = (uint32_t*)sml;              // 8192 u32 (32KB)
    const int w = threadIdx.x >> 5, lane = threadIdx.x & 31;

    #pragma unroll
    for (int rr = 0; rr < 2; rr++) {
        const int row = blockIdx.x * 16 + w * 2 + rr;
        const float* x = in + (size_t)row * C_;
        float4 v[8];
        float s = 0.f, ss = 0.f;
        #pragma unroll
        for (int i = 0; i < 8; i++) {
            v[i] = *(const float4*)(x + i * 128 + lane * 4);
            s += v[i].x + v[i].y + v[i].z + v[i].w;
            ss += v[i].x * v[i].x + v[i].y * v[i].y + v[i].z * v[i].z + v[i].w * v[i].w;
        }
        #pragma unroll
        for (int o = 16; o; o >>= 1) {
            s  += __shfl_xor_sync(0xffffffffu, s, o);
            ss += __shfl_xor_sync(0xffffffffu, ss, o);
        }
        float mean = s * (1.0f / C_);
        float rstd = rsqrtf(ss * (1.0f / C_) - mean * mean + EPS_);
        const int ag = row & 7, m8 = (row >> 3) & 1;
        const int kin = (lane & 3) * 4;
        const int tt0 = (kin & 7) >> 1, rk = kin >> 3;
        #pragma unroll
        for (int i = 0; i < 8; i++) {
            int c = i * 128 + lane * 4;
            float4 gv = *(const float4*)(gm + c);
            float4 bv = *(const float4*)(bt + c);
            float n0 = (v[i].x - mean) * rstd * gv.x + bv.x;
            float n1 = (v[i].y - mean) * rstd * gv.y + bv.y;
            float n2 = (v[i].z - mean) * rstd * gv.z + bv.z;
            float n3 = (v[i].w - mean) * rstd * gv.w + bv.w;
            int kt = c >> 4;
            int r = m8 + 2 * rk;
            sh[(kt * 32 + ag * 4 + tt0) * 4 + r] = packh2(n0, n1);
            sh[(kt * 32 + ag * 4 + tt0 + 1) * 4 + r] = packh2(n2, n3);
        }
    }
    __syncthreads();
    size_t gbase = (size_t)blockIdx.x * 8192;
    #pragma unroll
    for (int q = 0; q < 8; q++) {
        int i = q * 256 + threadIdx.x;
        *(uint4*)(outH + gbase + (size_t)i * 4) = ((const uint4*)sh)[i];
    }
}

// ========== weight prep: fp16 pack into B-fragment layout =========
__global__ void pack_weight(const float* __restrict__ W, uint32_t* __restrict__ hiP,
                            int K, int N) {
    int warp = threadIdx.x >> 5, lane = threadIdx.x & 31;
    int g = lane >> 2, t = lane & 3;
    int ktiles = K >> 4;
    int tiles = (N >> 3) * ktiles;
    for (int tile = blockIdx.x * 8 + warp; tile < tiles; tile += gridDim.x * 8) {
        int ntg = tile / ktiles, ksg = tile % ktiles;
        int n = ntg * 8 + g;
        #pragma unroll
        for (int reg = 0; reg < 2; reg++) {
            int k = ksg * 16 + 2 * t + reg * 8;
            float x0 = W[(size_t)k * N + n];
            float x1 = W[(size_t)(k + 1) * N + n];
            hiP[((size_t)tile * 32 + lane) * 2 + reg] = packh2(x0, x1);
        }
    }
}

// ======================= fp16 mma GEMM (packed A + packed B) ==========
// 128x128 CTA tile, K-step 32, 3-stage cp.async pipeline, 8 warps (2M x 4N).
// Stage (16KB): A[0,8K) B[8K,16K). 2 CTAs/SM (48KB x 2 smem, ~115 regs).
#define GM_STAGE 16384
#define GM_SMEM  (3 * GM_STAGE)

template <int EPI>
__global__ void __launch_bounds__(256, 2) gemm_mma(
    const uint32_t* __restrict__ AP, const uint32_t* __restrict__ BP,
    float* __restrict__ Cout, const float* __restrict__ bias,
    const float* __restrict__ res, uint32_t* __restrict__ OutHi,
    int M, int Nt, int K, const int* guard)
{
    if (guard && !guard[0]) return;
    extern __shared__ __align__(16) char smc[];
    const int tid = threadIdx.x;
    const int warp = tid >> 5, lane = tid & 31;
    const int g = lane >> 2, t = lane & 3;
    const int wm = warp & 1, wn = warp >> 1;
    const int bm = blockIdx.y * 128, bn = blockIdx.x * 128;
    const uint32_t sb = smem_u32(smc);

    const int NIT = K >> 5;
    const int ktiles = K >> 4;
    const int bm16 = bm >> 4, bn8 = bn >> 3;

    auto cpA = [&](int stage, int it) {
        uint32_t dstb = sb + stage * GM_STAGE;
        int kt0 = it * 2;
        #pragma unroll
        for (int q = 0; q < 2; q++) {
            int chunk = q * 256 + tid;        // 0..511
            int mtk = chunk >> 5, j = chunk & 31;
            int mtl = mtk >> 1, ktl = mtk & 1;
            size_t gidx = (((size_t)(bm16 + mtl) * ktiles + kt0 + ktl) * 32 + j) * 4;
            CP_ASYNC16(dstb + (uint32_t)(mtk * 512 + j * 16), AP + gidx);
        }
    };
    auto cpB = [&](int stage, int it) {
        uint32_t dstb = sb + stage * GM_STAGE + 8192u;
        int ksg0 = it * 2;
        #pragma unroll
        for (int q = 0; q < 2; q++) {
            int i = q * 256 + tid;            // 0..511
            int nt = i >> 5, j = i & 31;
            size_t srcoff = (((size_t)(bn8 + nt) * ktiles + ksg0) * 64 + (size_t)j * 4);
            CP_ASYNC16(dstb + (uint32_t)(nt * 512 + j * 16), BP + srcoff);
        }
    };

    float acc[4][4][4] = {};

    auto compute = [&](int stage) {
        char* base = smc + stage * GM_STAGE;
        #pragma unroll
        for (int ks = 0; ks < 2; ks++) {
            uint32_t ah[4][4], bh[4][2];
            #pragma unroll
            for (int mt = 0; mt < 4; mt++) {
                uint32_t off = (uint32_t)(((wm * 4 + mt) * 2 + ks) * 32 + lane) * 16;
                uint4 v = *(const uint4*)(base + off);
                ah[mt][0] = v.x; ah[mt][1] = v.y; ah[mt][2] = v.z; ah[mt][3] = v.w;
            }
            #pragma unroll
            for (int nt = 0; nt < 4; nt++) {
                uint32_t off = 8192u + (uint32_t)(((wn * 4 + nt) * 2 + ks) * 32 + lane) * 8;
                uint2 v = *(const uint2*)(base + off);
                bh[nt][0] = v.x; bh[nt][1] = v.y;
            }
            #pragma unroll
            for (int mt = 0; mt < 4; mt++)
                #pragma unroll
                for (int nt = 0; nt < 4; nt++)
                    mma_f16(acc[mt][nt], ah[mt], bh[nt]);
        }
    };

    cpA(0, 0); cpB(0, 0); CP_COMMIT();
    cpA(1, 1); cpB(1, 1); CP_COMMIT();

    int st = 0;
    for (int it = 0; it < NIT; it++) {
        if (it + 1 < NIT) { CP_WAIT1(); } else { CP_WAIT0(); }
        __syncthreads();
        if (it + 2 < NIT) {
            int ns = st + 2; if (ns >= 3) ns -= 3;
            cpA(ns, it + 2); cpB(ns, it + 2); CP_COMMIT();
        }
        compute(st);
        if (++st == 3) st = 0;
    }
    __syncthreads();

    if (EPI == 1) {
        #pragma unroll
        for (int mt = 0; mt < 4; mt++) {
            #pragma unroll
            for (int nt = 0; nt < 4; nt++) {
                int row0 = bm + wm * 64 + mt * 16 + g;
                int col = bn + wn * 32 + nt * 8 + t * 2;
                float2 bv = *(const float2*)&bias[col];
                float v0 = acc[mt][nt][0] + bv.x;
                float v1 = acc[mt][nt][1] + bv.y;
                float v2 = acc[mt][nt][2] + bv.x;
                float v3 = acc[mt][nt][3] + bv.y;
                size_t i0 = (size_t)row0 * Nt + col;
                size_t i1 = (size_t)(row0 + 8) * Nt + col;
                float2 r0 = *(const float2*)&res[i0];
                float2 r1 = *(const float2*)&res[i1];
                *(float2*)&Cout[i0] = make_float2(v0 + r0.x, v1 + r0.y);
                *(float2*)&Cout[i1] = make_float2(v2 + r1.x, v3 + r1.y);
            }
        }
    } else {
        // GELU -> packed fp16 A-fragments (32KB staged in smem)
        uint32_t* sh = (uint32_t*)smc;
        #pragma unroll
        for (int mt = 0; mt < 4; mt++) {
            #pragma unroll
            for (int nt = 0; nt < 4; nt++) {
                int kl = wn * 32 + nt * 8 + t * 2;
                float2 bv = *(const float2*)&bias[bn + kl];
                float v0 = acc[mt][nt][0] + bv.x;
                float v1 = acc[mt][nt][1] + bv.y;
                float v2 = acc[mt][nt][2] + bv.x;
                float v3 = acc[mt][nt][3] + bv.y;
                v0 = 0.5f * v0 * (1.0f + erff(v0 * 0.70710678118654752f));
                v1 = 0.5f * v1 * (1.0f + erff(v1 * 0.70710678118654752f));
                v2 = 0.5f * v2 * (1.0f + erff(v2 * 0.70710678118654752f));
                v3 = 0.5f * v3 * (1.0f + erff(v3 * 0.70710678118654752f));
                int mtl = wm * 4 + mt;
                int ktl = kl >> 4;
                int tt = (kl & 7) >> 1;
                int rk = (kl >> 3) & 1;
                int baseI = ((mtl * 8 + ktl) * 32 + g * 4 + tt) * 4;
                sh[baseI + 2 * rk] = packh2(v0, v1);
                sh[baseI + 1 + 2 * rk] = packh2(v2, v3);
            }
        }
        __syncthreads();
        const int ktO = Nt >> 4;
        #pragma unroll
        for (int q = 0; q < 8; q++) {
            int i = q * 256 + tid;             // 0..2047 uint4 slots
            int mtl = i >> 8, jj = i & 255;
            size_t gidx = (((size_t)(bm16 + mtl) * ktO + (bn >> 4)) * 128) + (size_t)jj * 4;
            *(uint4*)(OutHi + gidx) = ((const uint4*)sh)[i];
        }
    }
}

// ======================= fused flash attention (fp16 single-term) ===========
// grid (4 q-tiles, 8*NH). batch bb = blockIdx.y>>4 in 0..7 (x:0-3, y:4-7).
// KV batch = bb ^ kvxor. Output written as packed fp16 A-fragments.
#define FA_QH 0
#define FA_KH 16384
#define FA_VH 32768
#define FA_SMEM 49152

__global__ void __launch_bounds__(256, 1) fattn_kernel(
    const float* __restrict__ NA, int kvxor,
    uint32_t* __restrict__ Ohi, const int* guard)
{
    if (guard && !guard[0]) return;
    extern __shared__ __align__(16) char smf[];
    const int tid = threadIdx.x, lane = tid & 31, warp = tid >> 5;
    const int g = lane >> 2, t = lane & 3;
    const int bh = blockIdx.y, b = bh >> 4, h = bh & 15;
    const int n0 = blockIdx.x * 128;
    const float* Qb = NA + (size_t)b * N_ * C_ + h * D_;
    const float* Kb = NA + (size_t)(b ^ kvxor) * N_ * C_ + h * D_;

    // ---- Q -> fp16 A-fragments, scaled by 1/8 ----
    {
        const int arow = tid >> 1, hf = tid & 1;
        const float* qp = Qb + (size_t)(n0 + arow) * C_ + hf * 32;
        const int mtile = arow >> 4, ag = arow & 7, arm = (arow >> 3) & 1;
        #pragma unroll
        for (int q4 = 0; q4 < 8; q4++) {
            float4 v = *(const float4*)(qp + q4 * 4);
            float xs[4] = {v.x * 0.125f, v.y * 0.125f, v.z * 0.125f, v.w * 0.125f};
            #pragma unroll
            for (int p = 0; p < 2; p++) {
                int d = hf * 32 + q4 * 4 + 2 * p;
                int kt = d >> 4, kin = d & 15;
                int tt = (kin & 7) >> 1, rk = kin >> 3;
                uint32_t idx = (uint32_t)(((mtile * 4 + kt) * 32 + ag * 4 + tt) * 4 + (arm + 2 * rk));
                *(uint32_t*)(smf + FA_QH + idx * 4) = packh2(xs[2 * p], xs[2 * p + 1]);
            }
        }
    }
    __syncthreads();

    uint32_t qh[4][4];
    #pragma unroll
    for (int kt = 0; kt < 4; kt++) {
        uint4 v = *(const uint4*)(smf + FA_QH + (size_t)(((warp * 4 + kt) * 32 + lane) * 4) * 4);
        qh[kt][0] = v.x; qh[kt][1] = v.y; qh[kt][2] = v.z; qh[kt][3] = v.w;
    }

    float o[8][4] = {};
    float m0 = -1e30f, m1 = -1e30f, l0 = 0.f, l1 = 0.f;

    for (int ch = 0; ch < 4; ch++) {
        const int s0 = ch * 128;
        __syncthreads();
        // ---- K chunk -> fp16 B-frags ----
        {
            const int r = tid >> 1, hf = tid & 1;
            const float* kp = Kb + (size_t)(s0 + r) * C_ + hf * 32;
            const int ntile = r >> 3, kg = r & 7;
            #pragma unroll
            for (int q4 = 0; q4 < 8; q4++) {
                float4 v = *(const float4*)(kp + q4 * 4);
                float xs[4] = {v.x, v.y, v.z, v.w};
                #pragma unroll
                for (int p = 0; p < 2; p++) {
                    int d = hf * 32 + q4 * 4 + 2 * p;
                    int kt = d >> 4;
                    int lanef = kg * 4 + ((d & 7) >> 1);
                    int reg = ((d & 15) >= 8) ? 1 : 0;
                    uint32_t idx = (uint32_t)(((ntile * 4 + kt) * 32 + lanef) * 2 + reg);
                    *(uint32_t*)(smf + FA_KH + idx * 4) = packh2(xs[2 * p], xs[2 * p + 1]);
                }
            }
        }
        // ---- V chunk -> fp16 B-frags (n=d, k=s) ----
        {
            const int sp = tid & 63, dq = tid >> 6;
            const float* vp = Kb + (size_t)(s0 + 2 * sp) * C_ + dq * 16;
            #pragma unroll
            for (int q4 = 0; q4 < 4; q4++) {
                float4 a = *(const float4*)(vp + q4 * 4);
                float4 c = *(const float4*)(vp + C_ + q4 * 4);
                float as[4] = {a.x, a.y, a.z, a.w};
                float cs[4] = {c.x, c.y, c.z, c.w};
                #pragma unroll
                for (int e = 0; e < 4; e++) {
                    int d = dq * 16 + q4 * 4 + e;
                    int dnt = d >> 3, skt = sp >> 3;
                    int lanef = (d & 7) * 4 + (sp & 3);
                    int reg = (sp >> 2) & 1;
                    uint32_t idx = (uint32_t)(((dnt * 8 + skt) * 32 + lanef) * 2 + reg);
                    *(uint32_t*)(smf + FA_VH + idx * 4) = packh2(as[e], cs[e]);
                }
            }
        }
        __syncthreads();

        // ---- S = Q @ K^T (fp16) ----
        float s[16][4];
        #pragma unroll
        for (int nt = 0; nt < 16; nt++) { s[nt][0] = s[nt][1] = s[nt][2] = s[nt][3] = 0.f; }
        #pragma unroll
        for (int nt = 0; nt < 16; nt++) {
            #pragma unroll
            for (int kt = 0; kt < 4; kt++) {
                uint32_t kh[2];
                uint2 a = *(const uint2*)(smf + FA_KH + (size_t)(((nt * 4 + kt) * 32 + lane) * 2) * 4);
                kh[0] = a.x; kh[1] = a.y;
                mma_f16(s[nt], qh[kt], kh);
            }
        }

        // ---- online softmax ----
        float cm0 = -1e30f, cm1 = -1e30f;
        #pragma unroll
        for (int nt = 0; nt < 16; nt++) {
            cm0 = fmaxf(cm0, fmaxf(s[nt][0], s[nt][1]));
            cm1 = fmaxf(cm1, fmaxf(s[nt][2], s[nt][3]));
        }
        cm0 = fmaxf(cm0, __shfl_xor_sync(0xffffffffu, cm0, 1));
        cm0 = fmaxf(cm0, __shfl_xor_sync(0xffffffffu, cm0, 2));
        cm1 = fmaxf(cm1, __shfl_xor_sync(0xffffffffu, cm1, 1));
        cm1 = fmaxf(cm1, __shfl_xor_sync(0xffffffffu, cm1, 2));
        float nm0 = fmaxf(m0, cm0), nm1 = fmaxf(m1, cm1);
        float al0 = fast_exp(m0 - nm0), al1 = fast_exp(m1 - nm1);
        m0 = nm0; m1 = nm1;
        #pragma unroll
        for (int dnt = 0; dnt < 8; dnt++) {
            o[dnt][0] *= al0; o[dnt][1] *= al0;
            o[dnt][2] *= al1; o[dnt][3] *= al1;
        }
        float ls0 = 0.f, ls1 = 0.f;

        // ---- P = exp(S - m) (fp16 frags); PV mma ----
        #pragma unroll
        for (int kt = 0; kt < 8; kt++) {
            float p00 = fast_exp(s[2 * kt][0] - m0);
            float p01 = fast_exp(s[2 * kt][1] - m0);
            float p02 = fast_exp(s[2 * kt][2] - m1);
            float p03 = fast_exp(s[2 * kt][3] - m1);
            float p10 = fast_exp(s[2 * kt + 1][0] - m0);
            float p11 = fast_exp(s[2 * kt + 1][1] - m0);
            float p12 = fast_exp(s[2 * kt + 1][2] - m1);
            float p13 = fast_exp(s[2 * kt + 1][3] - m1);
            ls0 += p00 + p01 + p10 + p11;
            ls1 += p02 + p03 + p12 + p13;
            uint32_t ph[4];
            ph[0] = packh2(p00, p01);
            ph[1] = packh2(p02, p03);
            ph[2] = packh2(p10, p11);
            ph[3] = packh2(p12, p13);
            #pragma unroll
            for (int dnt = 0; dnt < 8; dnt++) {
                uint32_t vh[2];
                uint2 a = *(const uint2*)(smf + FA_VH + (size_t)(((dnt * 8 + kt) * 32 + lane) * 2) * 4);
                vh[0] = a.x; vh[1] = a.y;
                mma_f16(o[dnt], ph, vh);
            }
        }
        ls0 += __shfl_xor_sync(0xffffffffu, ls0, 1);
        ls0 += __shfl_xor_sync(0xffffffffu, ls0, 2);
        ls1 += __shfl_xor_sync(0xffffffffu, ls1, 1);
        ls1 += __shfl_xor_sync(0xffffffffu, ls1, 2);
        l0 = l0 * al0 + ls0;
        l1 = l1 * al1 + ls1;
    }

    // ---- packed fp16 epilogue ----
    __syncthreads();
    uint32_t* sh = (uint32_t*)(smf + FA_KH);   // 4096 u32 (16KB)
    float inv0 = 1.0f / l0, inv1 = 1.0f / l1;
    #pragma unroll
    for (int dnt = 0; dnt < 8; dnt++) {
        int kl_ = dnt * 8 + 2 * t;
        int ktl = kl_ >> 4;
        int rk = dnt & 1;
        int baseI = ((warp * 4 + ktl) * 32 + lane) * 4;
        sh[baseI + 2 * rk] = packh2(o[dnt][0] * inv0, o[dnt][1] * inv0);
        sh[baseI + 1 + 2 * rk] = packh2(o[dnt][2] * inv1, o[dnt][3] * inv1);
    }
    __syncthreads();
    #pragma unroll
    for (int q = 0; q < 4; q++) {
        int i = q * 256 + tid;
        int mtl = i >> 7, jj = i & 127;
        size_t gidx = (((size_t)(b * 32 + blockIdx.x * 8 + mtl) * 64) + h * 4) * 128 + (size_t)jj * 4;
        *(uint4*)(Ohi + gidx) = ((const uint4*)sh)[i];
    }
}

// ======================= host orchestration =======================
struct Weights {
    const float *n1g, *n1b, *n2g, *n2b, *pw, *pb, *w1, *b1, *w2, *b2;
};
struct Bufs {
    float *zb, *na;
    uint32_t *obh, *n2h, *hbh;
    uint32_t *pwh, *w1h, *w2h;
};

// One full transformer block over the batched 4096-row stream.
static void block_batched(float* resbuf, float* outbuf, int kvxor,
                          const Bufs& B, const Weights& W, const int* guard) {
    ln_kernel<<<R2_ / 16, 256>>>(resbuf, B.na, W.n1g, W.n1b, guard);
    fattn_kernel<<<dim3(4, 8 * NH_), 256, FA_SMEM>>>(B.na, kvxor, B.obh, guard);
    gemm_mma<1><<<dim3(C_ / 128, R2_ / 128), 256, GM_SMEM>>>(
        B.obh, B.pwh, outbuf, W.pb, resbuf, nullptr, R2_, C_, C_, guard);
    lnp_kernel<<<R2_ / 16, 256, 32768>>>(outbuf, B.n2h, W.n2g, W.n2b, guard);
    gemm_mma<2><<<dim3(HID_ / 128, R2_ / 128), 256, GM_SMEM>>>(
        B.n2h, B.w1h, nullptr, W.b1, nullptr, B.hbh, R2_, HID_, C_, guard);
    gemm_mma<1><<<dim3(C_ / 128, R2_ / 128), 256, GM_SMEM>>>(
        B.hbh, B.w2h, outbuf, W.b2, outbuf, nullptr, R2_, C_, HID_, guard);
}

extern "C" void kernel_launch(void* const* d_in, const int* in_sizes, int n_in,
                              void* d_out, int out_size) {
    const float* x   = (const float*)d_in[0];
    const float* y   = (const float*)d_in[1];
    Weights W;
    W.n1g = (const float*)d_in[2];  W.n1b = (const float*)d_in[3];
    W.n2g = (const float*)d_in[4];  W.n2b = (const float*)d_in[5];
    W.pw  = (const float*)d_in[6];  W.pb  = (const float*)d_in[7];
    W.w1  = (const float*)d_in[8];  W.b1  = (const float*)d_in[9];
    W.w2  = (const float*)d_in[10]; W.b2  = (const float*)d_in[11];
    const int* flag = (const int*)d_in[12];
    float* out = (float*)d_out;    // 4096 x 1024 = concat(x1, y1)

    Bufs B;
    cudaGetSymbolAddress((void**)&B.zb, g_zb);
    cudaGetSymbolAddress((void**)&B.na, g_na);
    cudaGetSymbolAddress((void**)&B.obh, g_obh);
    cudaGetSymbolAddress((void**)&B.n2h, g_n2h);
    cudaGetSymbolAddress((void**)&B.hbh, g_hbh);
    cudaGetSymbolAddress((void**)&B.pwh, g_pwh);
    cudaGetSymbolAddress((void**)&B.w1h, g_w1h);
    cudaGetSymbolAddress((void**)&B.w2h, g_w2h);

    cudaFuncSetAttribute(gemm_mma<1>, cudaFuncAttributeMaxDynamicSharedMemorySize, GM_SMEM);
    cudaFuncSetAttribute(gemm_mma<2>, cudaFuncAttributeMaxDynamicSharedMemorySize, GM_SMEM);
    cudaFuncSetAttribute(fattn_kernel, cudaFuncAttributeMaxDynamicSharedMemorySize, FA_SMEM);
    cudaFuncSetAttribute(lnp_kernel, cudaFuncAttributeMaxDynamicSharedMemorySize, 32768);

    // weight prep (runs every launch; ~15us)
    pack_weight<<<512, 256>>>(W.pw, B.pwh, C_, C_);
    pack_weight<<<512, 256>>>(W.w1, B.w1h, C_, HID_);
    pack_weight<<<512, 256>>>(W.w2, B.w2h, HID_, C_);

    const size_t bytes = (size_t)R_ * C_ * sizeof(float);
    cudaMemcpyAsync(B.zb, x, bytes, cudaMemcpyDeviceToDevice);
    cudaMemcpyAsync(B.zb + (size_t)R_ * C_, y, bytes, cudaMemcpyDeviceToDevice);

    // x and y self-chains batched as 8 "batches" (x:0-3, y:4-7). Only the
    // FINAL iteration's cross block is live: 4 gated self blocks, then one
    // cross block (kv from opposite half).
    for (int it = 0; it < 4; it++) {
        block_batched(B.zb, B.zb, 0, B, W, flag);
    }
    block_batched(B.zb, out, 4, B, W, nullptr);
}

// round 14
// speedup vs baseline: 2.6734x; 1.1182x over previous
#include <cuda_runtime.h>
#include <cuda_fp16.h>
#include <math.h>
#include <stdint.h>

// Problem dims (fixed by the dataset)
#define B_   4
#define N_   512
#define C_   1024
#define HID_ 4096
#define NH_  16
#define D_   64
#define R_   (B_*N_)     // 2048 rows per stream
#define R2_  (2*R_)      // 4096 rows: x-stream and y-stream batched
#define EPS_ 1e-5f

// ---------------- scratch (device globals: no allocation allowed) ----------
__device__ float g_zb[R2_*C_];    // concat(x, y) residual stream
// fp16 fragment buffers for attention (written by lnq_kernel)
__device__ uint32_t g_qf[R2_*C_/2];     // Q A-frags (scaled 1/8), per (16-row tile, head)
__device__ uint32_t g_kf[R2_*C_/2];     // K B-frags, per (8-row ntile, head)
__device__ uint32_t g_vf[R2_*C_/2];     // V B-frags, per (16-row vtile, head)
// fp16-packed (A-fragment layout) activations
__device__ uint32_t g_obh[R2_*C_/2];    // fattn out -> proj A
__device__ uint32_t g_n2h[R2_*C_/2];    // ln2 out   -> fc1 A
__device__ uint32_t g_hbh[R2_*HID_/2];  // gelu out  -> fc2 A
// fp16 weights packed in mma.m16n8k16 B-fragment layout
__device__ uint32_t g_pwh[C_*C_/2];
__device__ uint32_t g_w1h[C_*HID_/2];
__device__ uint32_t g_w2h[HID_*C_/2];

// ======================= helpers =======================
#define CP_ASYNC16(sm, gp) \
    asm volatile("cp.async.cg.shared.global [%0], [%1], 16;" :: "r"(sm), "l"(gp))
#define CP_COMMIT() asm volatile("cp.async.commit_group;" ::: "memory")
#define CP_WAIT0()  asm volatile("cp.async.wait_group 0;" ::: "memory")
#define CP_WAIT1()  asm volatile("cp.async.wait_group 1;" ::: "memory")

__device__ __forceinline__ uint32_t smem_u32(const void* p) {
    uint32_t a;
    asm("{ .reg .u64 t; cvta.to.shared.u64 t, %1; cvt.u32.u64 %0, t; }" : "=r"(a) : "l"(p));
    return a;
}

__device__ __forceinline__ uint32_t packh2(float a, float b) {
    __half2 h = __halves2half2(__float2half_rn(a), __float2half_rn(b));
    return *(uint32_t*)&h;
}

__device__ __forceinline__ void mma_f16(float* c, const uint32_t* a, const uint32_t* b) {
    asm volatile(
        "mma.sync.aligned.m16n8k16.row.col.f32.f16.f16.f32 "
        "{%0,%1,%2,%3}, {%4,%5,%6,%7}, {%8,%9}, {%0,%1,%2,%3};"
        : "+f"(c[0]), "+f"(c[1]), "+f"(c[2]), "+f"(c[3])
        : "r"(a[0]), "r"(a[1]), "r"(a[2]), "r"(a[3]), "r"(b[0]), "r"(b[1]));
}

__device__ __forceinline__ float fast_exp(float x) {
    float tt = fmaxf(x * 1.4426950408889634f, -126.0f);
    float fi = floorf(tt);
    float f = tt - fi;
    float p = 0.0013333558f;
    p = fmaf(p, f, 0.0096181291f);
    p = fmaf(p, f, 0.0555041087f);
    p = fmaf(p, f, 0.2402265070f);
    p = fmaf(p, f, 0.6931471806f);
    p = fmaf(p, f, 1.0f);
    return p * __int_as_float((__float2int_rn(fi) + 127) << 23);
}

// ===== LN1 -> Q/K/V fp16 fragment buffers (16 rows = 1 q/v tile, 2 k tiles) =
__global__ void __launch_bounds__(256) lnq_kernel(
    const float* __restrict__ in, uint32_t* __restrict__ qf,
    uint32_t* __restrict__ kf, uint32_t* __restrict__ vf,
    const float* __restrict__ gm, const float* __restrict__ bt,
    const int* guard)
{
    if (guard && !guard[0]) return;
    __shared__ uint32_t sh[8192];   // 32KB staging, reused 3x
    const int tid = threadIdx.x;
    const int w = tid >> 5, lane = tid & 31;
    const int row0 = blockIdx.x * 16 + w * 2;   // even row; warp owns rows row0, row0+1
    const float* x0 = in + (size_t)row0 * C_;
    const float* x1 = x0 + C_;

    float4 v0[8], v1[8];
    float s0 = 0.f, q0 = 0.f, s1 = 0.f, q1 = 0.f;
    #pragma unroll
    for (int i = 0; i < 8; i++) {
        v0[i] = *(const float4*)(x0 + i * 128 + lane * 4);
        s0 += v0[i].x + v0[i].y + v0[i].z + v0[i].w;
        q0 += v0[i].x * v0[i].x + v0[i].y * v0[i].y + v0[i].z * v0[i].z + v0[i].w * v0[i].w;
        v1[i] = *(const float4*)(x1 + i * 128 + lane * 4);
        s1 += v1[i].x + v1[i].y + v1[i].z + v1[i].w;
        q1 += v1[i].x * v1[i].x + v1[i].y * v1[i].y + v1[i].z * v1[i].z + v1[i].w * v1[i].w;
    }
    #pragma unroll
    for (int o = 16; o; o >>= 1) {
        s0 += __shfl_xor_sync(0xffffffffu, s0, o);
        q0 += __shfl_xor_sync(0xffffffffu, q0, o);
        s1 += __shfl_xor_sync(0xffffffffu, s1, o);
        q1 += __shfl_xor_sync(0xffffffffu, q1, o);
    }
    const float mn0 = s0 * (1.0f / C_);
    const float rs0 = rsqrtf(q0 * (1.0f / C_) - mn0 * mn0 + EPS_);
    const float mn1 = s1 * (1.0f / C_);
    const float rs1 = rsqrtf(q1 * (1.0f / C_) - mn1 * mn1 + EPS_);

    const int ag0 = row0 & 7;            // even; row1 has ag0+1
    const int arm = (row0 >> 3) & 1;     // same for both rows

    // ---- pass 1: Q A-fragments (scaled 1/8) ----
    #pragma unroll
    for (int i = 0; i < 8; i++) {
        int c = i * 128 + lane * 4;
        int h = c >> 6, d = c & 63;
        float4 gv = *(const float4*)(gm + c);
        float4 bv = *(const float4*)(bt + c);
        int kt = d >> 4;
        int tt = (d & 7) >> 1;
        int rk = (d & 15) >> 3;
        int bq = h * 512 + (kt * 32 + tt) * 4 + arm + 2 * rk;
        float a0 = ((v0[i].x - mn0) * rs0 * gv.x + bv.x) * 0.125f;
        float a1 = ((v0[i].y - mn0) * rs0 * gv.y + bv.y) * 0.125f;
        float a2 = ((v0[i].z - mn0) * rs0 * gv.z + bv.z) * 0.125f;
        float a3 = ((v0[i].w - mn0) * rs0 * gv.w + bv.w) * 0.125f;
        sh[bq + ag0 * 16] = packh2(a0, a1);
        sh[bq + ag0 * 16 + 4] = packh2(a2, a3);
        float c0 = ((v1[i].x - mn1) * rs1 * gv.x + bv.x) * 0.125f;
        float c1 = ((v1[i].y - mn1) * rs1 * gv.y + bv.y) * 0.125f;
        float c2 = ((v1[i].z - mn1) * rs1 * gv.z + bv.z) * 0.125f;
        float c3 = ((v1[i].w - mn1) * rs1 * gv.w + bv.w) * 0.125f;
        sh[bq + (ag0 + 1) * 16] = packh2(c0, c1);
        sh[bq + (ag0 + 1) * 16 + 4] = packh2(c2, c3);
    }
    __syncthreads();
    {
        size_t gb = (size_t)blockIdx.x * 8192;
        #pragma unroll
        for (int q = 0; q < 8; q++) {
            int i = q * 256 + tid;
            *(uint4*)(qf + gb + (size_t)i * 4) = ((const uint4*)sh)[i];
        }
    }
    __syncthreads();

    // ---- pass 2: K B-fragments (unscaled) ----
    {
        const int ntl = (row0 >> 3) & 1;
        #pragma unroll
        for (int i = 0; i < 8; i++) {
            int c = i * 128 + lane * 4;
            int h = c >> 6, d = c & 63;
            float4 gv = *(const float4*)(gm + c);
            float4 bv = *(const float4*)(bt + c);
            int kt = d >> 4;
            int lf = (d & 7) >> 1;     // + kg*4
            int reg = (d & 15) >> 3;
            int bk0 = (ntl * 16 + h) * 256 + kt * 64 + reg;
            float a0 = (v0[i].x - mn0) * rs0 * gv.x + bv.x;
            float a1 = (v0[i].y - mn0) * rs0 * gv.y + bv.y;
            float a2 = (v0[i].z - mn0) * rs0 * gv.z + bv.z;
            float a3 = (v0[i].w - mn0) * rs0 * gv.w + bv.w;
            sh[bk0 + (ag0 * 4 + lf) * 2] = packh2(a0, a1);
            sh[bk0 + (ag0 * 4 + lf + 1) * 2] = packh2(a2, a3);
            float c0 = (v1[i].x - mn1) * rs1 * gv.x + bv.x;
            float c1 = (v1[i].y - mn1) * rs1 * gv.y + bv.y;
            float c2 = (v1[i].z - mn1) * rs1 * gv.z + bv.z;
            float c3 = (v1[i].w - mn1) * rs1 * gv.w + bv.w;
            sh[bk0 + ((ag0 + 1) * 4 + lf) * 2] = packh2(c0, c1);
            sh[bk0 + ((ag0 + 1) * 4 + lf + 1) * 2] = packh2(c2, c3);
        }
    }
    __syncthreads();
    {
        size_t gb = (size_t)blockIdx.x * 8192;
        #pragma unroll
        for (int q = 0; q < 8; q++) {
            int i = q * 256 + tid;
            *(uint4*)(kf + gb + (size_t)i * 4) = ((const uint4*)sh)[i];
        }
    }
    __syncthreads();

    // ---- pass 3: V B-fragments (pairs across rows: (row0, row0+1)) ----
    {
        const int spw = w;                 // sp within 16-row tile = warp id
        const int reg = (spw >> 2) & 1;
        const int lt = spw & 3;
        #pragma unroll
        for (int i = 0; i < 8; i++) {
            int c = i * 128 + lane * 4;
            int h = c >> 6, d0 = c & 63;
            float4 gv = *(const float4*)(gm + c);
            float4 bv = *(const float4*)(bt + c);
            float a[4] = {
                (v0[i].x - mn0) * rs0 * gv.x + bv.x,
                (v0[i].y - mn0) * rs0 * gv.y + bv.y,
                (v0[i].z - mn0) * rs0 * gv.z + bv.z,
                (v0[i].w - mn0) * rs0 * gv.w + bv.w };
            float cc[4] = {
                (v1[i].x - mn1) * rs1 * gv.x + bv.x,
                (v1[i].y - mn1) * rs1 * gv.y + bv.y,
                (v1[i].z - mn1) * rs1 * gv.z + bv.z,
                (v1[i].w - mn1) * rs1 * gv.w + bv.w };
            #pragma unroll
            for (int e = 0; e < 4; e++) {
                int d = d0 + e;
                int dnt = d >> 3;
                int lanef = (d & 7) * 4 + lt;
                sh[h * 512 + (dnt * 32 + lanef) * 2 + reg] = packh2(a[e], cc[e]);
            }
        }
    }
    __syncthreads();
    {
        size_t gb = (size_t)blockIdx.x * 8192;
        #pragma unroll
        for (int q = 0; q < 8; q++) {
            int i = q * 256 + tid;
            *(uint4*)(vf + gb + (size_t)i * 4) = ((const uint4*)sh)[i];
        }
    }
}

// ============ LayerNorm -> packed fp16 A-fragments (for ln2 -> fc1) =========
__global__ void __launch_bounds__(256) lnp_kernel(
    const float* __restrict__ in, uint32_t* __restrict__ outH,
    const float* __restrict__ gm, const float* __restrict__ bt,
    const int* guard)
{
    if (guard && !guard[0]) return;
    extern __shared__ __align__(16) char sml[];
    uint32_t* sh = (uint32_t*)sml;
    const int w = threadIdx.x >> 5, lane = threadIdx.x & 31;
    #pragma unroll
    for (int rr = 0; rr < 2; rr++) {
        const int row = blockIdx.x * 16 + w * 2 + rr;
        const float* x = in + (size_t)row * C_;
        float4 v[8];
        float s = 0.f, ss = 0.f;
        #pragma unroll
        for (int i = 0; i < 8; i++) {
            v[i] = *(const float4*)(x + i * 128 + lane * 4);
            s += v[i].x + v[i].y + v[i].z + v[i].w;
            ss += v[i].x * v[i].x + v[i].y * v[i].y + v[i].z * v[i].z + v[i].w * v[i].w;
        }
        #pragma unroll
        for (int o = 16; o; o >>= 1) {
            s  += __shfl_xor_sync(0xffffffffu, s, o);
            ss += __shfl_xor_sync(0xffffffffu, ss, o);
        }
        float mean = s * (1.0f / C_);
        float rstd = rsqrtf(ss * (1.0f / C_) - mean * mean + EPS_);
        const int ag = row & 7, m8 = (row >> 3) & 1;
        const int kin = (lane & 3) * 4;
        const int tt0 = (kin & 7) >> 1, rk = kin >> 3;
        #pragma unroll
        for (int i = 0; i < 8; i++) {
            int c = i * 128 + lane * 4;
            float4 gv = *(const float4*)(gm + c);
            float4 bv = *(const float4*)(bt + c);
            float n0 = (v[i].x - mean) * rstd * gv.x + bv.x;
            float n1 = (v[i].y - mean) * rstd * gv.y + bv.y;
            float n2 = (v[i].z - mean) * rstd * gv.z + bv.z;
            float n3 = (v[i].w - mean) * rstd * gv.w + bv.w;
            int kt = c >> 4;
            int r = m8 + 2 * rk;
            sh[(kt * 32 + ag * 4 + tt0) * 4 + r] = packh2(n0, n1);
            sh[(kt * 32 + ag * 4 + tt0 + 1) * 4 + r] = packh2(n2, n3);
        }
    }
    __syncthreads();
    size_t gbase = (size_t)blockIdx.x * 8192;
    #pragma unroll
    for (int q = 0; q < 8; q++) {
        int i = q * 256 + threadIdx.x;
        *(uint4*)(outH + gbase + (size_t)i * 4) = ((const uint4*)sh)[i];
    }
}

// ========== weight prep: fp16 pack into B-fragment layout =========
__global__ void pack_weight(const float* __restrict__ W, uint32_t* __restrict__ hiP,
                            int K, int N) {
    int warp = threadIdx.x >> 5, lane = threadIdx.x & 31;
    int g = lane >> 2, t = lane & 3;
    int ktiles = K >> 4;
    int tiles = (N >> 3) * ktiles;
    for (int tile = blockIdx.x * 8 + warp; tile < tiles; tile += gridDim.x * 8) {
        int ntg = tile / ktiles, ksg = tile % ktiles;
        int n = ntg * 8 + g;
        #pragma unroll
        for (int reg = 0; reg < 2; reg++) {
            int k = ksg * 16 + 2 * t + reg * 8;
            float x0 = W[(size_t)k * N + n];
            float x1 = W[(size_t)(k + 1) * N + n];
            hiP[((size_t)tile * 32 + lane) * 2 + reg] = packh2(x0, x1);
        }
    }
}

// ======================= fp16 mma GEMM (packed A + packed B) ==========
#define GM_STAGE 16384
#define GM_SMEM  (3 * GM_STAGE)

template <int EPI>
__global__ void __launch_bounds__(256, 2) gemm_mma(
    const uint32_t* __restrict__ AP, const uint32_t* __restrict__ BP,
    float* __restrict__ Cout, const float* __restrict__ bias,
    const float* __restrict__ res, uint32_t* __restrict__ OutHi,
    int M, int Nt, int K, const int* guard)
{
    if (guard && !guard[0]) return;
    extern __shared__ __align__(16) char smc[];
    const int tid = threadIdx.x;
    const int warp = tid >> 5, lane = tid & 31;
    const int g = lane >> 2, t = lane & 3;
    const int wm = warp & 1, wn = warp >> 1;
    const int bm = blockIdx.y * 128, bn = blockIdx.x * 128;
    const uint32_t sb = smem_u32(smc);

    const int NIT = K >> 5;
    const int ktiles = K >> 4;
    const int bm16 = bm >> 4, bn8 = bn >> 3;

    auto cpA = [&](int stage, int it) {
        uint32_t dstb = sb + stage * GM_STAGE;
        int kt0 = it * 2;
        #pragma unroll
        for (int q = 0; q < 2; q++) {
            int chunk = q * 256 + tid;
            int mtk = chunk >> 5, j = chunk & 31;
            int mtl = mtk >> 1, ktl = mtk & 1;
            size_t gidx = (((size_t)(bm16 + mtl) * ktiles + kt0 + ktl) * 32 + j) * 4;
            CP_ASYNC16(dstb + (uint32_t)(mtk * 512 + j * 16), AP + gidx);
        }
    };
    auto cpB = [&](int stage, int it) {
        uint32_t dstb = sb + stage * GM_STAGE + 8192u;
        int ksg0 = it * 2;
        #pragma unroll
        for (int q = 0; q < 2; q++) {
            int i = q * 256 + tid;
            int nt = i >> 5, j = i & 31;
            size_t srcoff = (((size_t)(bn8 + nt) * ktiles + ksg0) * 64 + (size_t)j * 4);
            CP_ASYNC16(dstb + (uint32_t)(nt * 512 + j * 16), BP + srcoff);
        }
    };

    float acc[4][4][4] = {};

    auto compute = [&](int stage) {
        char* base = smc + stage * GM_STAGE;
        #pragma unroll
        for (int ks = 0; ks < 2; ks++) {
            uint32_t ah[4][4], bh[4][2];
            #pragma unroll
            for (int mt = 0; mt < 4; mt++) {
                uint32_t off = (uint32_t)(((wm * 4 + mt) * 2 + ks) * 32 + lane) * 16;
                uint4 v = *(const uint4*)(base + off);
                ah[mt][0] = v.x; ah[mt][1] = v.y; ah[mt][2] = v.z; ah[mt][3] = v.w;
            }
            #pragma unroll
            for (int nt = 0; nt < 4; nt++) {
                uint32_t off = 8192u + (uint32_t)(((wn * 4 + nt) * 2 + ks) * 32 + lane) * 8;
                uint2 v = *(const uint2*)(base + off);
                bh[nt][0] = v.x; bh[nt][1] = v.y;
            }
            #pragma unroll
            for (int mt = 0; mt < 4; mt++)
                #pragma unroll
                for (int nt = 0; nt < 4; nt++)
                    mma_f16(acc[mt][nt], ah[mt], bh[nt]);
        }
    };

    cpA(0, 0); cpB(0, 0); CP_COMMIT();
    cpA(1, 1); cpB(1, 1); CP_COMMIT();

    int st = 0;
    for (int it = 0; it < NIT; it++) {
        if (it + 1 < NIT) { CP_WAIT1(); } else { CP_WAIT0(); }
        __syncthreads();
        if (it + 2 < NIT) {
            int ns = st + 2; if (ns >= 3) ns -= 3;
            cpA(ns, it + 2); cpB(ns, it + 2); CP_COMMIT();
        }
        compute(st);
        if (++st == 3) st = 0;
    }
    __syncthreads();

    if (EPI == 1) {
        #pragma unroll
        for (int mt = 0; mt < 4; mt++) {
            #pragma unroll
            for (int nt = 0; nt < 4; nt++) {
                int row0 = bm + wm * 64 + mt * 16 + g;
                int col = bn + wn * 32 + nt * 8 + t * 2;
                float2 bv = *(const float2*)&bias[col];
                float v0 = acc[mt][nt][0] + bv.x;
                float v1 = acc[mt][nt][1] + bv.y;
                float v2 = acc[mt][nt][2] + bv.x;
                float v3 = acc[mt][nt][3] + bv.y;
                size_t i0 = (size_t)row0 * Nt + col;
                size_t i1 = (size_t)(row0 + 8) * Nt + col;
                float2 r0 = *(const float2*)&res[i0];
                float2 r1 = *(const float2*)&res[i1];
                *(float2*)&Cout[i0] = make_float2(v0 + r0.x, v1 + r0.y);
                *(float2*)&Cout[i1] = make_float2(v2 + r1.x, v3 + r1.y);
            }
        }
    } else {
        uint32_t* sh = (uint32_t*)smc;
        #pragma unroll
        for (int mt = 0; mt < 4; mt++) {
            #pragma unroll
            for (int nt = 0; nt < 4; nt++) {
                int kl = wn * 32 + nt * 8 + t * 2;
                float2 bv = *(const float2*)&bias[bn + kl];
                float v0 = acc[mt][nt][0] + bv.x;
                float v1 = acc[mt][nt][1] + bv.y;
                float v2 = acc[mt][nt][2] + bv.x;
                float v3 = acc[mt][nt][3] + bv.y;
                v0 = 0.5f * v0 * (1.0f + erff(v0 * 0.70710678118654752f));
                v1 = 0.5f * v1 * (1.0f + erff(v1 * 0.70710678118654752f));
                v2 = 0.5f * v2 * (1.0f + erff(v2 * 0.70710678118654752f));
                v3 = 0.5f * v3 * (1.0f + erff(v3 * 0.70710678118654752f));
                int mtl = wm * 4 + mt;
                int ktl = kl >> 4;
                int tt = (kl & 7) >> 1;
                int rk = (kl >> 3) & 1;
                int baseI = ((mtl * 8 + ktl) * 32 + g * 4 + tt) * 4;
                sh[baseI + 2 * rk] = packh2(v0, v1);
                sh[baseI + 1 + 2 * rk] = packh2(v2, v3);
            }
        }
        __syncthreads();
        const int ktO = Nt >> 4;
        #pragma unroll
        for (int q = 0; q < 8; q++) {
            int i = q * 256 + tid;
            int mtl = i >> 8, jj = i & 255;
            size_t gidx = (((size_t)(bm16 + mtl) * ktO + (bn >> 4)) * 128) + (size_t)jj * 4;
            *(uint4*)(OutHi + gidx) = ((const uint4*)sh)[i];
        }
    }
}

// ============ flash attention: pure cp.async fragments + fp16 mma ===========
// grid (4 q-tiles, 8*NH). KV batch = b ^ kvxor. 3-stage KV pipeline.
#define FQ_OFF  0
#define FSTG(st) (16384 + (st) * 32768)
#define FA_SMEM (16384 + 3 * 32768)   // 112KB

__global__ void __launch_bounds__(256, 1) fattn_kernel(
    const uint32_t* __restrict__ qf, const uint32_t* __restrict__ kf,
    const uint32_t* __restrict__ vf, int kvxor,
    uint32_t* __restrict__ Ohi, const int* guard)
{
    if (guard && !guard[0]) return;
    extern __shared__ __align__(16) char smf[];
    const uint32_t sb = smem_u32(smf);
    const int tid = threadIdx.x, lane = tid & 31, warp = tid >> 5;
    const int g = lane >> 2, t = lane & 3;
    const int bh = blockIdx.y, b = bh >> 4, h = bh & 15;
    const int bk = b ^ kvxor;
    const int n0 = blockIdx.x * 128;
    const int qt0 = (b * N_ + n0) >> 4;

    auto cpQ = [&]() {
        #pragma unroll
        for (int q = 0; q < 4; q++) {
            int slot = q * 256 + tid;
            int tile = slot >> 7, j = slot & 127;
            CP_ASYNC16(sb + FQ_OFF + (uint32_t)slot * 16,
                       qf + ((size_t)(qt0 + tile) * 16 + h) * 512 + (size_t)j * 4);
        }
    };
    auto cpK = [&](int st, int ch) {
        int nt0 = (bk * N_ + ch * 128) >> 3;
        #pragma unroll
        for (int q = 0; q < 4; q++) {
            int slot = q * 256 + tid;
            int ntl = slot >> 6, j = slot & 63;
            CP_ASYNC16(sb + FSTG(st) + (uint32_t)slot * 16,
                       kf + ((size_t)(nt0 + ntl) * 16 + h) * 256 + (size_t)j * 4);
        }
    };
    auto cpV = [&](int st, int ch) {
        int vt0 = (bk * N_ + ch * 128) >> 4;
        #pragma unroll
        for (int q = 0; q < 4; q++) {
            int slot = q * 256 + tid;
            int dnt = slot >> 7, rem = slot & 127;
            int skt = rem >> 4, w16 = rem & 15;
            CP_ASYNC16(sb + FSTG(st) + 16384u + (uint32_t)slot * 16,
                       vf + ((size_t)(vt0 + skt) * 16 + h) * 512 + dnt * 64 + (size_t)w16 * 4);
        }
    };

    cpQ(); cpK(0, 0); cpV(0, 0); CP_COMMIT();
    cpK(1, 1); cpV(1, 1); CP_COMMIT();

    uint32_t qh[4][4];
    float o[8][4] = {};
    float m0 = -1e30f, m1 = -1e30f, l0 = 0.f, l1 = 0.f;

    int st = 0;
    for (int ch = 0; ch < 4; ch++) {
        if (ch + 1 < 4) { CP_WAIT1(); } else { CP_WAIT0(); }
        __syncthreads();
        if (ch == 0) {
            #pragma unroll
            for (int kt = 0; kt < 4; kt++) {
                uint4 v = *(const uint4*)(smf + FQ_OFF + (size_t)(((warp * 4 + kt) * 32 + lane) * 4) * 4);
                qh[kt][0] = v.x; qh[kt][1] = v.y; qh[kt][2] = v.z; qh[kt][3] = v.w;
            }
        }
        if (ch + 2 < 4) {
            int ns = st + 2; if (ns >= 3) ns -= 3;
            cpK(ns, ch + 2); cpV(ns, ch + 2); CP_COMMIT();
        }
        const char* kb = smf + FSTG(st);
        const char* vb = smf + FSTG(st) + 16384;

        // ---- S = Q @ K^T ----
        float s[16][4];
        #pragma unroll
        for (int nt = 0; nt < 16; nt++) { s[nt][0] = s[nt][1] = s[nt][2] = s[nt][3] = 0.f; }
        #pragma unroll
        for (int nt = 0; nt < 16; nt++) {
            #pragma unroll
            for (int kt = 0; kt < 4; kt++) {
                uint32_t kh[2];
                uint2 a = *(const uint2*)(kb + (size_t)(((nt * 4 + kt) * 32 + lane) * 2) * 4);
                kh[0] = a.x; kh[1] = a.y;
                mma_f16(s[nt], qh[kt], kh);
            }
        }

        // ---- online softmax ----
        float cm0 = -1e30f, cm1 = -1e30f;
        #pragma unroll
        for (int nt = 0; nt < 16; nt++) {
            cm0 = fmaxf(cm0, fmaxf(s[nt][0], s[nt][1]));
            cm1 = fmaxf(cm1, fmaxf(s[nt][2], s[nt][3]));
        }
        cm0 = fmaxf(cm0, __shfl_xor_sync(0xffffffffu, cm0, 1));
        cm0 = fmaxf(cm0, __shfl_xor_sync(0xffffffffu, cm0, 2));
        cm1 = fmaxf(cm1, __shfl_xor_sync(0xffffffffu, cm1, 1));
        cm1 = fmaxf(cm1, __shfl_xor_sync(0xffffffffu, cm1, 2));
        float nm0 = fmaxf(m0, cm0), nm1 = fmaxf(m1, cm1);
        float al0 = fast_exp(m0 - nm0), al1 = fast_exp(m1 - nm1);
        m0 = nm0; m1 = nm1;
        #pragma unroll
        for (int dnt = 0; dnt < 8; dnt++) {
            o[dnt][0] *= al0; o[dnt][1] *= al0;
            o[dnt][2] *= al1; o[dnt][3] *= al1;
        }
        float ls0 = 0.f, ls1 = 0.f;

        #pragma unroll
        for (int kt = 0; kt < 8; kt++) {
            float p00 = fast_exp(s[2 * kt][0] - m0);
            float p01 = fast_exp(s[2 * kt][1] - m0);
            float p02 = fast_exp(s[2 * kt][2] - m1);
            float p03 = fast_exp(s[2 * kt][3] - m1);
            float p10 = fast_exp(s[2 * kt + 1][0] - m0);
            float p11 = fast_exp(s[2 * kt + 1][1] - m0);
            float p12 = fast_exp(s[2 * kt + 1][2] - m1);
            float p13 = fast_exp(s[2 * kt + 1][3] - m1);
            ls0 += p00 + p01 + p10 + p11;
            ls1 += p02 + p03 + p12 + p13;
            uint32_t ph[4];
            ph[0] = packh2(p00, p01);
            ph[1] = packh2(p02, p03);
            ph[2] = packh2(p10, p11);
            ph[3] = packh2(p12, p13);
            #pragma unroll
            for (int dnt = 0; dnt < 8; dnt++) {
                uint32_t vh[2];
                uint2 a = *(const uint2*)(vb + (size_t)(((dnt * 8 + kt) * 32 + lane) * 2) * 4);
                vh[0] = a.x; vh[1] = a.y;
                mma_f16(o[dnt], ph, vh);
            }
        }
        ls0 += __shfl_xor_sync(0xffffffffu, ls0, 1);
        ls0 += __shfl_xor_sync(0xffffffffu, ls0, 2);
        ls1 += __shfl_xor_sync(0xffffffffu, ls1, 1);
        ls1 += __shfl_xor_sync(0xffffffffu, ls1, 2);
        l0 = l0 * al0 + ls0;
        l1 = l1 * al1 + ls1;
        if (++st == 3) st = 0;
    }

    // ---- packed fp16 epilogue (reuse stage-0 K region) ----
    __syncthreads();
    uint32_t* sh = (uint32_t*)(smf + FSTG(0));
    float inv0 = 1.0f / l0, inv1 = 1.0f / l1;
    #pragma unroll
    for (int dnt = 0; dnt < 8; dnt++) {
        int kl_ = dnt * 8 + 2 * t;
        int ktl = kl_ >> 4;
        int rk = dnt & 1;
        int baseI = ((warp * 4 + ktl) * 32 + lane) * 4;
        sh[baseI + 2 * rk] = packh2(o[dnt][0] * inv0, o[dnt][1] * inv0);
        sh[baseI + 1 + 2 * rk] = packh2(o[dnt][2] * inv1, o[dnt][3] * inv1);
    }
    __syncthreads();
    #pragma unroll
    for (int q = 0; q < 4; q++) {
        int i = q * 256 + tid;
        int mtl = i >> 7, jj = i & 127;
        size_t gidx = (((size_t)(b * 32 + blockIdx.x * 8 + mtl) * 64) + h * 4) * 128 + (size_t)jj * 4;
        *(uint4*)(Ohi + gidx) = ((const uint4*)sh)[i];
    }
}

// ======================= host orchestration =======================
struct Weights {
    const float *n1g, *n1b, *n2g, *n2b, *pw, *pb, *w1, *b1, *w2, *b2;
};
struct Bufs {
    float *zb;
    uint32_t *qf, *kf, *vf;
    uint32_t *obh, *n2h, *hbh;
    uint32_t *pwh, *w1h, *w2h;
};

// One full transformer block over the batched 4096-row stream.
static void block_batched(float* resbuf, float* outbuf, int kvxor,
                          const Bufs& B, const Weights& W, const int* guard) {
    lnq_kernel<<<R2_ / 16, 256>>>(resbuf, B.qf, B.kf, B.vf, W.n1g, W.n1b, guard);
    fattn_kernel<<<dim3(4, 8 * NH_), 256, FA_SMEM>>>(B.qf, B.kf, B.vf, kvxor, B.obh, guard);
    gemm_mma<1><<<dim3(C_ / 128, R2_ / 128), 256, GM_SMEM>>>(
        B.obh, B.pwh, outbuf, W.pb, resbuf, nullptr, R2_, C_, C_, guard);
    lnp_kernel<<<R2_ / 16, 256, 32768>>>(outbuf, B.n2h, W.n2g, W.n2b, guard);
    gemm_mma<2><<<dim3(HID_ / 128, R2_ / 128), 256, GM_SMEM>>>(
        B.n2h, B.w1h, nullptr, W.b1, nullptr, B.hbh, R2_, HID_, C_, guard);
    gemm_mma<1><<<dim3(C_ / 128, R2_ / 128), 256, GM_SMEM>>>(
        B.hbh, B.w2h, outbuf, W.b2, outbuf, nullptr, R2_, C_, HID_, guard);
}

extern "C" void kernel_launch(void* const* d_in, const int* in_sizes, int n_in,
                              void* d_out, int out_size) {
    const float* x   = (const float*)d_in[0];
    const float* y   = (const float*)d_in[1];
    Weights W;
    W.n1g = (const float*)d_in[2];  W.n1b = (const float*)d_in[3];
    W.n2g = (const float*)d_in[4];  W.n2b = (const float*)d_in[5];
    W.pw  = (const float*)d_in[6];  W.pb  = (const float*)d_in[7];
    W.w1  = (const float*)d_in[8];  W.b1  = (const float*)d_in[9];
    W.w2  = (const float*)d_in[10]; W.b2  = (const float*)d_in[11];
    const int* flag = (const int*)d_in[12];
    float* out = (float*)d_out;    // 4096 x 1024 = concat(x1, y1)

    Bufs B;
    cudaGetSymbolAddress((void**)&B.zb, g_zb);
    cudaGetSymbolAddress((void**)&B.qf, g_qf);
    cudaGetSymbolAddress((void**)&B.kf, g_kf);
    cudaGetSymbolAddress((void**)&B.vf, g_vf);
    cudaGetSymbolAddress((void**)&B.obh, g_obh);
    cudaGetSymbolAddress((void**)&B.n2h, g_n2h);
    cudaGetSymbolAddress((void**)&B.hbh, g_hbh);
    cudaGetSymbolAddress((void**)&B.pwh, g_pwh);
    cudaGetSymbolAddress((void**)&B.w1h, g_w1h);
    cudaGetSymbolAddress((void**)&B.w2h, g_w2h);

    cudaFuncSetAttribute(gemm_mma<1>, cudaFuncAttributeMaxDynamicSharedMemorySize, GM_SMEM);
    cudaFuncSetAttribute(gemm_mma<2>, cudaFuncAttributeMaxDynamicSharedMemorySize, GM_SMEM);
    cudaFuncSetAttribute(fattn_kernel, cudaFuncAttributeMaxDynamicSharedMemorySize, FA_SMEM);
    cudaFuncSetAttribute(lnp_kernel, cudaFuncAttributeMaxDynamicSharedMemorySize, 32768);

    // weight prep (runs every launch; ~15us)
    pack_weight<<<512, 256>>>(W.pw, B.pwh, C_, C_);
    pack_weight<<<512, 256>>>(W.w1, B.w1h, C_, HID_);
    pack_weight<<<512, 256>>>(W.w2, B.w2h, HID_, C_);

    const size_t bytes = (size_t)R_ * C_ * sizeof(float);
    cudaMemcpyAsync(B.zb, x, bytes, cudaMemcpyDeviceToDevice);
    cudaMemcpyAsync(B.zb + (size_t)R_ * C_, y, bytes, cudaMemcpyDeviceToDevice);

    // x and y self-chains batched as 8 "batches" (x:0-3, y:4-7). Only the
    // FINAL iteration's cross block is live: 4 gated self blocks, then one
    // cross block (kv from opposite half).
    for (int it = 0; it < 4; it++) {
        block_batched(B.zb, B.zb, 0, B, W, flag);
    }
    block_batched(B.zb, out, 4, B, W, nullptr);
}